// round 2
// baseline (speedup 1.0000x reference)
#include <cuda_runtime.h>
#include <cuda_bf16.h>
#include <math.h>

// Problem constants
#define R_DIM 128
#define C_DIM 256
#define E_DIM 768
#define H_DIM 12
#define D_DIM 64
#define M_TOK (R_DIM * C_DIM)          // 32768 tokens
#define SCALING 0.125f                  // 64^-0.5

// Scratch (device globals; zero-init .bss, no allocation)
__device__ float g_q[M_TOK * E_DIM];
__device__ float g_k[M_TOK * E_DIM];
__device__ float g_v[M_TOK * E_DIM];
__device__ float g_ctx[M_TOK * E_DIM];

// ---------------------------------------------------------------------------
// GEMM: C[m,n] = (sum_k A[m,k] * W[n,k] + bias[n]) * scale
// A: [M,K] row-major, W: [N,K] row-major. M%128==0, N%128==0, K%8==0.
// BM=128 BN=128 BK=8, 256 threads, 8x8 per-thread tile, warps 2(M)x4(N).
// ---------------------------------------------------------------------------
__global__ __launch_bounds__(256) void gemm_bias_kernel(
    const float* __restrict__ A, const float* __restrict__ W,
    const float* __restrict__ bias, float* __restrict__ C,
    int M, int N, int K, float scale)
{
    __shared__ float As[8][128];
    __shared__ float Bs[8][128];

    const int m0 = blockIdx.y * 128;
    const int n0 = blockIdx.x * 128;
    const int t = threadIdx.x;
    const int lane = t & 31, warp = t >> 5;
    const int wm = warp & 1, wn = warp >> 1;    // 2 x 4 warps
    const int lr = lane >> 2, lc = lane & 3;    // 8 x 4 lanes
    const int ri = wm * 64 + lr * 8;            // row frag base in tile
    const int ci = wn * 32 + lc * 8;            // col frag base in tile

    const int lrow = t >> 1, lseg = t & 1;
    const float* Aptr = A + (size_t)(m0 + lrow) * K + lseg * 4;
    const float* Wptr = W + (size_t)(n0 + lrow) * K + lseg * 4;

    float acc[8][8];
#pragma unroll
    for (int r = 0; r < 8; r++)
#pragma unroll
        for (int c = 0; c < 8; c++) acc[r][c] = 0.0f;

    for (int k0 = 0; k0 < K; k0 += 8) {
        float4 av = *(const float4*)(Aptr + k0);
        float4 wv = *(const float4*)(Wptr + k0);
        As[lseg * 4 + 0][lrow] = av.x;
        As[lseg * 4 + 1][lrow] = av.y;
        As[lseg * 4 + 2][lrow] = av.z;
        As[lseg * 4 + 3][lrow] = av.w;
        Bs[lseg * 4 + 0][lrow] = wv.x;
        Bs[lseg * 4 + 1][lrow] = wv.y;
        Bs[lseg * 4 + 2][lrow] = wv.z;
        Bs[lseg * 4 + 3][lrow] = wv.w;
        __syncthreads();

#pragma unroll
        for (int kk = 0; kk < 8; kk++) {
            float a[8], b[8];
            *(float4*)(a)     = *(const float4*)&As[kk][ri];
            *(float4*)(a + 4) = *(const float4*)&As[kk][ri + 4];
            *(float4*)(b)     = *(const float4*)&Bs[kk][ci];
            *(float4*)(b + 4) = *(const float4*)&Bs[kk][ci + 4];
#pragma unroll
            for (int r = 0; r < 8; r++)
#pragma unroll
                for (int c = 0; c < 8; c++)
                    acc[r][c] += a[r] * b[c];
        }
        __syncthreads();
    }

    // epilogue: (acc + bias) * scale
#pragma unroll
    for (int r = 0; r < 8; r++) {
        float* outp = C + (size_t)(m0 + ri + r) * N + n0 + ci;
#pragma unroll
        for (int cc = 0; cc < 8; cc += 4) {
            float4 o;
            o.x = (acc[r][cc + 0] + bias[n0 + ci + cc + 0]) * scale;
            o.y = (acc[r][cc + 1] + bias[n0 + ci + cc + 1]) * scale;
            o.z = (acc[r][cc + 2] + bias[n0 + ci + cc + 2]) * scale;
            o.w = (acc[r][cc + 3] + bias[n0 + ci + cc + 3]) * scale;
            *(float4*)(outp + cc) = o;
        }
    }
}

// ---------------------------------------------------------------------------
// Attention: one block per (c, h). 256 threads.
// SMEM (floats): QT[64][132] @0, KT[64][132] @8448  (aliased by ST[128][132] @0)
//                VS[128][68] @16896.  Total 25600 floats = 100 KB dynamic.
// ---------------------------------------------------------------------------
#define SMEM_ATT_FLOATS 25600
#define QT_OFF 0
#define KT_OFF 8448
#define ST_OFF 0
#define VS_OFF 16896

__global__ __launch_bounds__(256) void attn_kernel(
    const float* __restrict__ Q, const float* __restrict__ K,
    const float* __restrict__ V, const int* __restrict__ mask,
    float* __restrict__ probs, float* __restrict__ ctx)
{
    extern __shared__ float sm[];
    float* QT = sm + QT_OFF;
    float* KT = sm + KT_OFF;
    float* ST = sm + ST_OFF;
    float* VS = sm + VS_OFF;

    const int c = blockIdx.x;
    const int h = blockIdx.y;
    const int t = threadIdx.x;
    const int lane = t & 31, warp = t >> 5;

    // ---- load Q,K transposed [d][i], V row-major [j][d] ----
    {
        const int i = t >> 1, seg = t & 1;
        const size_t base = (size_t)i * (C_DIM * E_DIM) + (size_t)c * E_DIM + h * D_DIM + seg * 32;
        const float* qrow = Q + base;
        const float* krow = K + base;
        const float* vrow = V + base;
#pragma unroll
        for (int u = 0; u < 8; u++) {
            const int d = seg * 32 + u * 4;
            float4 qv = *(const float4*)(qrow + u * 4);
            QT[(d + 0) * 132 + i] = qv.x;
            QT[(d + 1) * 132 + i] = qv.y;
            QT[(d + 2) * 132 + i] = qv.z;
            QT[(d + 3) * 132 + i] = qv.w;
            float4 kv = *(const float4*)(krow + u * 4);
            KT[(d + 0) * 132 + i] = kv.x;
            KT[(d + 1) * 132 + i] = kv.y;
            KT[(d + 2) * 132 + i] = kv.z;
            KT[(d + 3) * 132 + i] = kv.w;
            *(float4*)&VS[i * 68 + d] = *(const float4*)(vrow + u * 4);
        }
    }
    __syncthreads();

    // ---- scores S[i][j] = sum_d QT[d][i]*KT[d][j]  (Q pre-scaled) ----
    const int wm = warp & 1, wn = warp >> 1;   // 2 x 4
    const int lr = lane >> 2, lc = lane & 3;   // 8 x 4
    const int i0 = wm * 64 + lr * 8;
    const int j0 = wn * 32 + lc * 8;

    float acc[8][8];
#pragma unroll
    for (int r = 0; r < 8; r++)
#pragma unroll
        for (int cc = 0; cc < 8; cc++) acc[r][cc] = 0.0f;

#pragma unroll 4
    for (int d = 0; d < 64; d++) {
        float a[8], b[8];
        *(float4*)(a)     = *(const float4*)&QT[d * 132 + i0];
        *(float4*)(a + 4) = *(const float4*)&QT[d * 132 + i0 + 4];
        *(float4*)(b)     = *(const float4*)&KT[d * 132 + j0];
        *(float4*)(b + 4) = *(const float4*)&KT[d * 132 + j0 + 4];
#pragma unroll
        for (int r = 0; r < 8; r++)
#pragma unroll
            for (int cc = 0; cc < 8; cc++)
                acc[r][cc] += a[r] * b[cc];
    }
    __syncthreads();   // done reading QT/KT; ST aliases them

    // ---- write scores transposed ST[j][i], applying column mask ----
    const bool masked = (mask[c] != 0);
#pragma unroll
    for (int cc = 0; cc < 8; cc++) {
        float* dst = &ST[(j0 + cc) * 132 + i0];
#pragma unroll
        for (int r = 0; r < 8; r += 4) {
            float4 o;
            o.x = masked ? -10000.0f : acc[r + 0][cc];
            o.y = masked ? -10000.0f : acc[r + 1][cc];
            o.z = masked ? -10000.0f : acc[r + 2][cc];
            o.w = masked ? -10000.0f : acc[r + 3][cc];
            *(float4*)(dst + r) = o;
        }
    }
    __syncthreads();

    // ---- softmax over j (ST column scans are conflict-free) ----
    if (t < 128) {
        const int i = t;
        float mx = -1e30f;
        for (int j = 0; j < 128; j++) mx = fmaxf(mx, ST[j * 132 + i]);
        float s = 0.0f;
        for (int j = 0; j < 128; j++) {
            float e = __expf(ST[j * 132 + i] - mx);
            s += e;
            ST[j * 132 + i] = e;
        }
        float inv = 1.0f / s;
        for (int j = 0; j < 128; j++) ST[j * 132 + i] *= inv;
    }
    __syncthreads();

    // ---- write attn_probs [h][c][i][j] (read-only on ST; no sync needed after) ----
    {
        const size_t pbase = (size_t)(h * C_DIM + c) * (R_DIM * R_DIM);
        for (int idx = t; idx < 4096; idx += 256) {
            const int i = idx >> 5;
            const int j4 = (idx & 31) * 4;
            float4 o;
            o.x = ST[(j4 + 0) * 132 + i];
            o.y = ST[(j4 + 1) * 132 + i];
            o.z = ST[(j4 + 2) * 132 + i];
            o.w = ST[(j4 + 3) * 132 + i];
            *(float4*)(probs + pbase + (size_t)i * 128 + j4) = o;
        }
    }

    // ---- context: ctx[i][d] = sum_j P[i][j] * V[j][d] ----
    // warps 2(i) x 4(d); lanes 8(i) x 4(d); thread tile 8x4.
    const int i0c = wm * 64 + lr * 8;
    const int d0c = (warp >> 1) * 16 + lc * 4;

    float acc2[8][4];
#pragma unroll
    for (int r = 0; r < 8; r++)
#pragma unroll
        for (int u = 0; u < 4; u++) acc2[r][u] = 0.0f;

#pragma unroll 4
    for (int j = 0; j < 128; j++) {
        float a[8], b[4];
        *(float4*)(a)     = *(const float4*)&ST[j * 132 + i0c];
        *(float4*)(a + 4) = *(const float4*)&ST[j * 132 + i0c + 4];
        *(float4*)(b)     = *(const float4*)&VS[j * 68 + d0c];
#pragma unroll
        for (int r = 0; r < 8; r++)
#pragma unroll
            for (int u = 0; u < 4; u++)
                acc2[r][u] += a[r] * b[u];
    }

#pragma unroll
    for (int r = 0; r < 8; r++) {
        const size_t off = ((size_t)(i0c + r) * C_DIM + c) * E_DIM + h * D_DIM + d0c;
        float4 o;
        o.x = acc2[r][0]; o.y = acc2[r][1]; o.z = acc2[r][2]; o.w = acc2[r][3];
        *(float4*)(ctx + off) = o;
    }
}

// ---------------------------------------------------------------------------
extern "C" void kernel_launch(void* const* d_in, const int* in_sizes, int n_in,
                              void* d_out, int out_size)
{
    const float* x  = (const float*)d_in[0];
    const int*   mask = (const int*)d_in[1];    // jax bool -> int32 in harness
    const float* wq = (const float*)d_in[2];
    const float* bq = (const float*)d_in[3];
    const float* wk = (const float*)d_in[4];
    const float* bk = (const float*)d_in[5];
    const float* wv = (const float*)d_in[6];
    const float* bv = (const float*)d_in[7];
    const float* wo = (const float*)d_in[8];
    const float* bo = (const float*)d_in[9];

    float* out   = (float*)d_out;                                  // [128,256,1,768]
    float* probs = (float*)d_out + (size_t)M_TOK * E_DIM;          // [12,256,1,128,128]

    float *pq, *pk, *pv, *pctx;
    cudaGetSymbolAddress((void**)&pq,  g_q);
    cudaGetSymbolAddress((void**)&pk,  g_k);
    cudaGetSymbolAddress((void**)&pv,  g_v);
    cudaGetSymbolAddress((void**)&pctx, g_ctx);

    static bool attr_set = false;
    if (!attr_set) {
        cudaFuncSetAttribute(attn_kernel, cudaFuncAttributeMaxDynamicSharedMemorySize,
                             SMEM_ATT_FLOATS * sizeof(float));
        attr_set = true;
    }

    dim3 gproj(E_DIM / 128, M_TOK / 128);   // (6, 256)
    gemm_bias_kernel<<<gproj, 256>>>(x, wq, bq, pq, M_TOK, E_DIM, E_DIM, SCALING);
    gemm_bias_kernel<<<gproj, 256>>>(x, wk, bk, pk, M_TOK, E_DIM, E_DIM, 1.0f);
    gemm_bias_kernel<<<gproj, 256>>>(x, wv, bv, pv, M_TOK, E_DIM, E_DIM, 1.0f);

    dim3 gattn(C_DIM, H_DIM);               // (256, 12)
    attn_kernel<<<gattn, 256, SMEM_ATT_FLOATS * sizeof(float)>>>(
        pq, pk, pv, mask, probs, pctx);

    gemm_bias_kernel<<<gproj, 256>>>(pctx, wo, bo, out, M_TOK, E_DIM, E_DIM, 1.0f);
}

// round 4
// speedup vs baseline: 2.3489x; 2.3489x over previous
#include <cuda_runtime.h>
#include <cuda_bf16.h>
#include <cstdint>
#include <math.h>

// Problem constants
#define R_DIM 128
#define C_DIM 256
#define E_DIM 768
#define H_DIM 12
#define D_DIM 64
#define M_TOK (R_DIM * C_DIM)          // 32768
#define SCALING 0.125f

// fp32 scratch
__device__ __align__(128) float g_q[M_TOK * E_DIM];
__device__ __align__(128) float g_k[M_TOK * E_DIM];
__device__ __align__(128) float g_v[M_TOK * E_DIM];
__device__ __align__(128) float g_ctx[M_TOK * E_DIM];
// bf16 hi/lo splits
__device__ __align__(128) __nv_bfloat16 g_xh[M_TOK * E_DIM];
__device__ __align__(128) __nv_bfloat16 g_xl[M_TOK * E_DIM];
__device__ __align__(128) __nv_bfloat16 g_ch[M_TOK * E_DIM];
__device__ __align__(128) __nv_bfloat16 g_cl[M_TOK * E_DIM];
__device__ __align__(128) __nv_bfloat16 g_wh[4][E_DIM * E_DIM];
__device__ __align__(128) __nv_bfloat16 g_wl[4][E_DIM * E_DIM];

// ---------------------------------------------------------------------------
// Helpers
// ---------------------------------------------------------------------------
__device__ __forceinline__ uint32_t smem_u32(const void* p) {
    uint32_t a;
    asm("{ .reg .u64 t; cvta.to.shared.u64 t, %1; cvt.u32.u64 %0, t; }" : "=r"(a) : "l"(p));
    return a;
}
__device__ __forceinline__ void cp_async16(uint32_t s, const void* g) {
    size_t ga = __cvta_generic_to_global(g);
    asm volatile("cp.async.cg.shared.global [%0], [%1], 16;" :: "r"(s), "l"(ga));
}
__device__ __forceinline__ void cp_commit() { asm volatile("cp.async.commit_group;" ::: "memory"); }
template <int N> __device__ __forceinline__ void cp_wait() {
    asm volatile("cp.async.wait_group %0;" :: "n"(N) : "memory");
}
__device__ __forceinline__ void ldmx4(uint32_t* r, uint32_t addr) {
    asm volatile("ldmatrix.sync.aligned.m8n8.x4.shared.b16 {%0,%1,%2,%3}, [%4];"
        : "=r"(r[0]), "=r"(r[1]), "=r"(r[2]), "=r"(r[3]) : "r"(addr));
}
__device__ __forceinline__ void mma16816(float* c, const uint32_t* a, const uint32_t* b) {
    asm volatile("mma.sync.aligned.m16n8k16.row.col.f32.bf16.bf16.f32 "
        "{%0,%1,%2,%3}, {%4,%5,%6,%7}, {%8,%9}, {%0,%1,%2,%3};"
        : "+f"(c[0]), "+f"(c[1]), "+f"(c[2]), "+f"(c[3])
        : "r"(a[0]), "r"(a[1]), "r"(a[2]), "r"(a[3]), "r"(b[0]), "r"(b[1]));
}

#define SMEM_SWZ(o) ((o) ^ (((o) >> 3) & 0x70))

// ---------------------------------------------------------------------------
// Split fp32 -> bf16 hi + bf16 lo
// ---------------------------------------------------------------------------
__global__ __launch_bounds__(256) void split_kernel(
    const float* __restrict__ in, __nv_bfloat16* __restrict__ hi,
    __nv_bfloat16* __restrict__ lo, int n4)
{
    for (int i = blockIdx.x * blockDim.x + threadIdx.x; i < n4; i += gridDim.x * blockDim.x) {
        float4 v = ((const float4*)in)[i];
        __nv_bfloat16 h[4], l[4];
        h[0] = __float2bfloat16(v.x); l[0] = __float2bfloat16(v.x - __bfloat162float(h[0]));
        h[1] = __float2bfloat16(v.y); l[1] = __float2bfloat16(v.y - __bfloat162float(h[1]));
        h[2] = __float2bfloat16(v.z); l[2] = __float2bfloat16(v.z - __bfloat162float(h[2]));
        h[3] = __float2bfloat16(v.w); l[3] = __float2bfloat16(v.w - __bfloat162float(h[3]));
        ((uint2*)hi)[i] = *(uint2*)h;
        ((uint2*)lo)[i] = *(uint2*)l;
    }
}

// ---------------------------------------------------------------------------
// mma.sync GEMM: C[m,n] = (sum_k A[m,k]*W[n,k] + bias[n]) * scale
// A ~ Ah+Al, W ~ Wh+Wl (bf16). BM=128, BN=128, BK=64, 256 thr, 2x4 warps,
// warp tile 64x32, frags m16n8k16. 3 MMA terms: hh + hl + lh.
// ---------------------------------------------------------------------------
#define GK 768
#define BM 128
#define BN 128
#define BK 64
#define NCHUNK (GK / BK)                 // 12
#define BUF_BYTES (128 * 128)            // 16384 per bf16 buffer (128 rows x 128B)
#define STAGE_BYTES (4 * BUF_BYTES)      // Ah, Al, Bh, Bl = 64KB
#define GEMM_SMEM (2 * STAGE_BYTES + 2048)

__device__ __forceinline__ void load_chunk(
    uint32_t stage,
    const __nv_bfloat16* __restrict__ Ah, const __nv_bfloat16* __restrict__ Al,
    const __nv_bfloat16* __restrict__ Bh, const __nv_bfloat16* __restrict__ Bl,
    int m0, int n0, int kc, int t)
{
#pragma unroll
    for (int p = 0; p < 4; p++) {               // A: 128 rows x 8 segs of 16B
        int u = t + p * 256;
        int row = u >> 3, seg = u & 7;
        size_t go = (size_t)(m0 + row) * GK + kc + seg * 8;
        uint32_t so = SMEM_SWZ(row * 128 + seg * 16);
        cp_async16(stage + so, Ah + go);
        cp_async16(stage + BUF_BYTES + so, Al + go);
    }
#pragma unroll
    for (int p = 0; p < 4; p++) {               // B: 128 rows x 8 segs
        int u = t + p * 256;
        int row = u >> 3, seg = u & 7;
        size_t go = (size_t)(n0 + row) * GK + kc + seg * 8;
        uint32_t so = SMEM_SWZ(row * 128 + seg * 16);
        cp_async16(stage + 2 * BUF_BYTES + so, Bh + go);
        cp_async16(stage + 3 * BUF_BYTES + so, Bl + go);
    }
}

__global__ __launch_bounds__(256, 1)
void gemm_tc_kernel(
    const __nv_bfloat16* __restrict__ Ah, const __nv_bfloat16* __restrict__ Al,
    const __nv_bfloat16* __restrict__ Bh, const __nv_bfloat16* __restrict__ Bl,
    const float* __restrict__ bias, float* __restrict__ C, float scale)
{
    extern __shared__ char smbuf[];
    const uint32_t tiles = (smem_u32(smbuf) + 1023) & ~1023u;
    const int t = threadIdx.x;
    const int lane = t & 31, wid = t >> 5;
    const int wm = wid & 1, wn = wid >> 1;      // 2(M) x 4(N) warps
    const int n0 = blockIdx.x * BN;
    const int m0 = blockIdx.y * BM;

    const uint32_t stg[2] = { tiles, tiles + STAGE_BYTES };

    // lane-derived ldmatrix row/col offsets
    const int a_row = lane & 15;
    const int a_k8 = (lane >> 4) * 8;                       // 0/8
    const int b_row = (lane & 7) + ((lane >> 4) & 1) * 8;   // n within n16
    const int b_k8 = ((lane >> 3) & 1) * 8;

    float acc[4][4][4];
#pragma unroll
    for (int mt = 0; mt < 4; mt++)
#pragma unroll
        for (int nt = 0; nt < 4; nt++)
#pragma unroll
            for (int q = 0; q < 4; q++) acc[mt][nt][q] = 0.0f;

    // prologue
    load_chunk(stg[0], Ah, Al, Bh, Bl, m0, n0, 0, t);
    cp_commit();

    for (int c = 0; c < NCHUNK; c++) {
        const int s = c & 1;
        cp_wait<0>();
        __syncthreads();
        if (c + 1 < NCHUNK) {
            load_chunk(stg[s ^ 1], Ah, Al, Bh, Bl, m0, n0, (c + 1) * BK, t);
            cp_commit();
        }

        const uint32_t Abase = stg[s];
        const uint32_t Bbase = stg[s] + 2 * BUF_BYTES;
#pragma unroll
        for (int kk = 0; kk < 4; kk++) {
            uint32_t ah[4][4], al[4][4];
#pragma unroll
            for (int mt = 0; mt < 4; mt++) {
                uint32_t off = (uint32_t)(wm * 64 + mt * 16 + a_row) * 128
                             + (kk * 16 + a_k8) * 2;
                uint32_t sw = SMEM_SWZ(off);
                ldmx4(ah[mt], Abase + sw);
                ldmx4(al[mt], Abase + BUF_BYTES + sw);
            }
            uint32_t bh[2][4], bl[2][4];
#pragma unroll
            for (int nb = 0; nb < 2; nb++) {
                uint32_t off = (uint32_t)(wn * 32 + nb * 16 + b_row) * 128
                             + (kk * 16 + b_k8) * 2;
                uint32_t sw = SMEM_SWZ(off);
                ldmx4(bh[nb], Bbase + sw);
                ldmx4(bl[nb], Bbase + BUF_BYTES + sw);
            }
#pragma unroll
            for (int mt = 0; mt < 4; mt++)
#pragma unroll
                for (int nt = 0; nt < 4; nt++) {
                    const uint32_t* fh = &bh[nt >> 1][(nt & 1) * 2];
                    const uint32_t* fl = &bl[nt >> 1][(nt & 1) * 2];
                    mma16816(acc[mt][nt], ah[mt], fh);
                    mma16816(acc[mt][nt], ah[mt], fl);
                    mma16816(acc[mt][nt], al[mt], fh);
                }
        }
        __syncthreads();
    }

    // epilogue: (acc + bias) * scale, direct to global
#pragma unroll
    for (int mt = 0; mt < 4; mt++) {
        const int m = m0 + wm * 64 + mt * 16 + (lane >> 2);
#pragma unroll
        for (int nt = 0; nt < 4; nt++) {
            const int n = n0 + wn * 32 + nt * 8 + (lane & 3) * 2;
            const float b0 = bias[n], b1 = bias[n + 1];
            float2 o0, o1;
            o0.x = (acc[mt][nt][0] + b0) * scale;
            o0.y = (acc[mt][nt][1] + b1) * scale;
            o1.x = (acc[mt][nt][2] + b0) * scale;
            o1.y = (acc[mt][nt][3] + b1) * scale;
            *(float2*)(C + (size_t)m * GK + n) = o0;
            *(float2*)(C + (size_t)(m + 8) * GK + n) = o1;
        }
    }
}

// ---------------------------------------------------------------------------
// Attention: one block per (c, h). 256 threads. (unchanged — known good)
// ---------------------------------------------------------------------------
#define SMEM_ATT_FLOATS 25600
#define QT_OFF 0
#define KT_OFF 8448
#define ST_OFF 0
#define VS_OFF 16896

__global__ __launch_bounds__(256) void attn_kernel(
    const float* __restrict__ Q, const float* __restrict__ K,
    const float* __restrict__ V, const int* __restrict__ mask,
    float* __restrict__ probs, float* __restrict__ ctx)
{
    extern __shared__ float sm[];
    float* QT = sm + QT_OFF;
    float* KT = sm + KT_OFF;
    float* ST = sm + ST_OFF;
    float* VS = sm + VS_OFF;

    const int c = blockIdx.x;
    const int h = blockIdx.y;
    const int t = threadIdx.x;
    const int lane = t & 31, warp = t >> 5;

    {
        const int i = t >> 1, seg = t & 1;
        const size_t base = (size_t)i * (C_DIM * E_DIM) + (size_t)c * E_DIM + h * D_DIM + seg * 32;
        const float* qrow = Q + base;
        const float* krow = K + base;
        const float* vrow = V + base;
#pragma unroll
        for (int u = 0; u < 8; u++) {
            const int d = seg * 32 + u * 4;
            float4 qv = *(const float4*)(qrow + u * 4);
            QT[(d + 0) * 132 + i] = qv.x;
            QT[(d + 1) * 132 + i] = qv.y;
            QT[(d + 2) * 132 + i] = qv.z;
            QT[(d + 3) * 132 + i] = qv.w;
            float4 kv = *(const float4*)(krow + u * 4);
            KT[(d + 0) * 132 + i] = kv.x;
            KT[(d + 1) * 132 + i] = kv.y;
            KT[(d + 2) * 132 + i] = kv.z;
            KT[(d + 3) * 132 + i] = kv.w;
            *(float4*)&VS[i * 68 + d] = *(const float4*)(vrow + u * 4);
        }
    }
    __syncthreads();

    const int wm = warp & 1, wn = warp >> 1;
    const int lr = lane >> 2, lc = lane & 3;
    const int i0 = wm * 64 + lr * 8;
    const int j0 = wn * 32 + lc * 8;

    float acc[8][8];
#pragma unroll
    for (int r = 0; r < 8; r++)
#pragma unroll
        for (int cc = 0; cc < 8; cc++) acc[r][cc] = 0.0f;

#pragma unroll 4
    for (int d = 0; d < 64; d++) {
        float a[8], b[8];
        *(float4*)(a)     = *(const float4*)&QT[d * 132 + i0];
        *(float4*)(a + 4) = *(const float4*)&QT[d * 132 + i0 + 4];
        *(float4*)(b)     = *(const float4*)&KT[d * 132 + j0];
        *(float4*)(b + 4) = *(const float4*)&KT[d * 132 + j0 + 4];
#pragma unroll
        for (int r = 0; r < 8; r++)
#pragma unroll
            for (int cc = 0; cc < 8; cc++)
                acc[r][cc] += a[r] * b[cc];
    }
    __syncthreads();

    const bool masked = (mask[c] != 0);
#pragma unroll
    for (int cc = 0; cc < 8; cc++) {
        float* dst = &ST[(j0 + cc) * 132 + i0];
#pragma unroll
        for (int r = 0; r < 8; r += 4) {
            float4 o;
            o.x = masked ? -10000.0f : acc[r + 0][cc];
            o.y = masked ? -10000.0f : acc[r + 1][cc];
            o.z = masked ? -10000.0f : acc[r + 2][cc];
            o.w = masked ? -10000.0f : acc[r + 3][cc];
            *(float4*)(dst + r) = o;
        }
    }
    __syncthreads();

    if (t < 128) {
        const int i = t;
        float mx = -1e30f;
        for (int j = 0; j < 128; j++) mx = fmaxf(mx, ST[j * 132 + i]);
        float s = 0.0f;
        for (int j = 0; j < 128; j++) {
            float e = __expf(ST[j * 132 + i] - mx);
            s += e;
            ST[j * 132 + i] = e;
        }
        float inv = 1.0f / s;
        for (int j = 0; j < 128; j++) ST[j * 132 + i] *= inv;
    }
    __syncthreads();

    {
        const size_t pbase = (size_t)(h * C_DIM + c) * (R_DIM * R_DIM);
        for (int idx = t; idx < 4096; idx += 256) {
            const int i = idx >> 5;
            const int j4 = (idx & 31) * 4;
            float4 o;
            o.x = ST[(j4 + 0) * 132 + i];
            o.y = ST[(j4 + 1) * 132 + i];
            o.z = ST[(j4 + 2) * 132 + i];
            o.w = ST[(j4 + 3) * 132 + i];
            *(float4*)(probs + pbase + (size_t)i * 128 + j4) = o;
        }
    }

    const int i0c = wm * 64 + lr * 8;
    const int d0c = (warp >> 1) * 16 + lc * 4;

    float acc2[8][4];
#pragma unroll
    for (int r = 0; r < 8; r++)
#pragma unroll
        for (int u = 0; u < 4; u++) acc2[r][u] = 0.0f;

#pragma unroll 4
    for (int j = 0; j < 128; j++) {
        float a[8], b[4];
        *(float4*)(a)     = *(const float4*)&ST[j * 132 + i0c];
        *(float4*)(a + 4) = *(const float4*)&ST[j * 132 + i0c + 4];
        *(float4*)(b)     = *(const float4*)&VS[j * 68 + d0c];
#pragma unroll
        for (int r = 0; r < 8; r++)
#pragma unroll
            for (int u = 0; u < 4; u++)
                acc2[r][u] += a[r] * b[u];
    }

#pragma unroll
    for (int r = 0; r < 8; r++) {
        const size_t off = ((size_t)(i0c + r) * C_DIM + c) * E_DIM + h * D_DIM + d0c;
        float4 o;
        o.x = acc2[r][0]; o.y = acc2[r][1]; o.z = acc2[r][2]; o.w = acc2[r][3];
        *(float4*)(ctx + off) = o;
    }
}

// ---------------------------------------------------------------------------
extern "C" void kernel_launch(void* const* d_in, const int* in_sizes, int n_in,
                              void* d_out, int out_size)
{
    const float* x  = (const float*)d_in[0];
    const int*   mask = (const int*)d_in[1];
    const float* wq = (const float*)d_in[2];
    const float* bq = (const float*)d_in[3];
    const float* wk = (const float*)d_in[4];
    const float* bk = (const float*)d_in[5];
    const float* wv = (const float*)d_in[6];
    const float* bv = (const float*)d_in[7];
    const float* wo = (const float*)d_in[8];
    const float* bo = (const float*)d_in[9];

    float* out   = (float*)d_out;
    float* probs = (float*)d_out + (size_t)M_TOK * E_DIM;

    float *pq, *pk, *pv, *pctx;
    __nv_bfloat16 *xh, *xl, *ch, *cl, *wh, *wl;
    cudaGetSymbolAddress((void**)&pq,  g_q);
    cudaGetSymbolAddress((void**)&pk,  g_k);
    cudaGetSymbolAddress((void**)&pv,  g_v);
    cudaGetSymbolAddress((void**)&pctx, g_ctx);
    cudaGetSymbolAddress((void**)&xh, g_xh);
    cudaGetSymbolAddress((void**)&xl, g_xl);
    cudaGetSymbolAddress((void**)&ch, g_ch);
    cudaGetSymbolAddress((void**)&cl, g_cl);
    cudaGetSymbolAddress((void**)&wh, g_wh);
    cudaGetSymbolAddress((void**)&wl, g_wl);

    static bool attr_set = false;
    if (!attr_set) {
        cudaFuncSetAttribute(attn_kernel, cudaFuncAttributeMaxDynamicSharedMemorySize,
                             SMEM_ATT_FLOATS * sizeof(float));
        cudaFuncSetAttribute(gemm_tc_kernel, cudaFuncAttributeMaxDynamicSharedMemorySize,
                             GEMM_SMEM);
        attr_set = true;
    }

    const int NW = E_DIM * E_DIM;       // 589824
    const int NX = M_TOK * E_DIM;       // 25165824

    split_kernel<<<4096, 256>>>(x, xh, xl, NX / 4);
    split_kernel<<<576, 256>>>(wq, wh + 0 * (size_t)NW, wl + 0 * (size_t)NW, NW / 4);
    split_kernel<<<576, 256>>>(wk, wh + 1 * (size_t)NW, wl + 1 * (size_t)NW, NW / 4);
    split_kernel<<<576, 256>>>(wv, wh + 2 * (size_t)NW, wl + 2 * (size_t)NW, NW / 4);
    split_kernel<<<576, 256>>>(wo, wh + 3 * (size_t)NW, wl + 3 * (size_t)NW, NW / 4);

    dim3 gg(E_DIM / BN, M_TOK / BM);    // (6, 256)
    gemm_tc_kernel<<<gg, 256, GEMM_SMEM>>>(xh, xl, wh + 0 * (size_t)NW, wl + 0 * (size_t)NW,
                                           bq, pq, SCALING);
    gemm_tc_kernel<<<gg, 256, GEMM_SMEM>>>(xh, xl, wh + 1 * (size_t)NW, wl + 1 * (size_t)NW,
                                           bk, pk, 1.0f);
    gemm_tc_kernel<<<gg, 256, GEMM_SMEM>>>(xh, xl, wh + 2 * (size_t)NW, wl + 2 * (size_t)NW,
                                           bv, pv, 1.0f);

    dim3 gattn(C_DIM, H_DIM);
    attn_kernel<<<gattn, 256, SMEM_ATT_FLOATS * sizeof(float)>>>(
        pq, pk, pv, mask, probs, pctx);

    split_kernel<<<4096, 256>>>(pctx, ch, cl, NX / 4);
    gemm_tc_kernel<<<gg, 256, GEMM_SMEM>>>(ch, cl, wh + 3 * (size_t)NW, wl + 3 * (size_t)NW,
                                           bo, out, 1.0f);
}

// round 5
// speedup vs baseline: 2.8509x; 1.2137x over previous
#include <cuda_runtime.h>
#include <cuda_bf16.h>
#include <cstdint>
#include <math.h>

// Problem constants
#define R_DIM 128
#define C_DIM 256
#define E_DIM 768
#define H_DIM 12
#define D_DIM 64
#define M_TOK (R_DIM * C_DIM)          // 32768
#define SCALING 0.125f

// bf16 hi/lo scratch (device globals; no allocation)
__device__ __align__(128) __nv_bfloat16 g_xh[M_TOK * E_DIM];
__device__ __align__(128) __nv_bfloat16 g_xl[M_TOK * E_DIM];
__device__ __align__(128) __nv_bfloat16 g_qh[M_TOK * E_DIM];
__device__ __align__(128) __nv_bfloat16 g_ql[M_TOK * E_DIM];
__device__ __align__(128) __nv_bfloat16 g_kh[M_TOK * E_DIM];
__device__ __align__(128) __nv_bfloat16 g_kl[M_TOK * E_DIM];
__device__ __align__(128) __nv_bfloat16 g_vh[M_TOK * E_DIM];
__device__ __align__(128) __nv_bfloat16 g_vl[M_TOK * E_DIM];
__device__ __align__(128) __nv_bfloat16 g_ch[M_TOK * E_DIM];
__device__ __align__(128) __nv_bfloat16 g_cl[M_TOK * E_DIM];
__device__ __align__(128) __nv_bfloat16 g_wh[4][E_DIM * E_DIM];
__device__ __align__(128) __nv_bfloat16 g_wl[4][E_DIM * E_DIM];

// ---------------------------------------------------------------------------
// Helpers
// ---------------------------------------------------------------------------
__device__ __forceinline__ uint32_t smem_u32(const void* p) {
    uint32_t a;
    asm("{ .reg .u64 t; cvta.to.shared.u64 t, %1; cvt.u32.u64 %0, t; }" : "=r"(a) : "l"(p));
    return a;
}
__device__ __forceinline__ void cp_async16(uint32_t s, const void* g) {
    size_t ga = __cvta_generic_to_global(g);
    asm volatile("cp.async.cg.shared.global [%0], [%1], 16;" :: "r"(s), "l"(ga));
}
__device__ __forceinline__ void cp_commit() { asm volatile("cp.async.commit_group;" ::: "memory"); }
template <int N> __device__ __forceinline__ void cp_wait() {
    asm volatile("cp.async.wait_group %0;" :: "n"(N) : "memory");
}
__device__ __forceinline__ void ldmx4(uint32_t* r, uint32_t addr) {
    asm volatile("ldmatrix.sync.aligned.m8n8.x4.shared.b16 {%0,%1,%2,%3}, [%4];"
        : "=r"(r[0]), "=r"(r[1]), "=r"(r[2]), "=r"(r[3]) : "r"(addr));
}
__device__ __forceinline__ void mma16816(float* c, const uint32_t* a, const uint32_t* b) {
    asm volatile("mma.sync.aligned.m16n8k16.row.col.f32.bf16.bf16.f32 "
        "{%0,%1,%2,%3}, {%4,%5,%6,%7}, {%8,%9}, {%0,%1,%2,%3};"
        : "+f"(c[0]), "+f"(c[1]), "+f"(c[2]), "+f"(c[3])
        : "r"(a[0]), "r"(a[1]), "r"(a[2]), "r"(a[3]), "r"(b[0]), "r"(b[1]));
}
// split two floats -> packed bf16x2 hi and lo
__device__ __forceinline__ void split2(float f0, float f1, uint32_t& hi, uint32_t& lo) {
    __nv_bfloat16 h0 = __float2bfloat16(f0);
    __nv_bfloat16 h1 = __float2bfloat16(f1);
    __nv_bfloat16 l0 = __float2bfloat16(f0 - __bfloat162float(h0));
    __nv_bfloat16 l1 = __float2bfloat16(f1 - __bfloat162float(h1));
    __nv_bfloat162 hp = { h0, h1 }, lp = { l0, l1 };
    hi = *(uint32_t*)&hp;
    lo = *(uint32_t*)&lp;
}

#define SMEM_SWZ(o) ((o) ^ (((o) >> 3) & 0x70))

// ---------------------------------------------------------------------------
// Split fp32 -> bf16 hi + bf16 lo
// ---------------------------------------------------------------------------
__global__ __launch_bounds__(256) void split_kernel(
    const float* __restrict__ in, __nv_bfloat16* __restrict__ hi,
    __nv_bfloat16* __restrict__ lo, int n4)
{
    for (int i = blockIdx.x * blockDim.x + threadIdx.x; i < n4; i += gridDim.x * blockDim.x) {
        float4 v = ((const float4*)in)[i];
        __nv_bfloat16 h[4], l[4];
        h[0] = __float2bfloat16(v.x); l[0] = __float2bfloat16(v.x - __bfloat162float(h[0]));
        h[1] = __float2bfloat16(v.y); l[1] = __float2bfloat16(v.y - __bfloat162float(h[1]));
        h[2] = __float2bfloat16(v.z); l[2] = __float2bfloat16(v.z - __bfloat162float(h[2]));
        h[3] = __float2bfloat16(v.w); l[3] = __float2bfloat16(v.w - __bfloat162float(h[3]));
        ((uint2*)hi)[i] = *(uint2*)h;
        ((uint2*)lo)[i] = *(uint2*)l;
    }
}

// ---------------------------------------------------------------------------
// mma.sync GEMM: acc = sum_k A[m,k]*W[n,k]; out = (acc + bias[n]) * scale
// If Ch != nullptr: write bf16 hi/lo split; else write fp32 to C.
// BM=BN=128, BK=64, 256 thr, 2x4 warps, warp tile 64x32, 3 terms hh+hl+lh.
// ---------------------------------------------------------------------------
#define GK 768
#define BM 128
#define BN 128
#define BK 64
#define NCHUNK (GK / BK)                 // 12
#define BUF_BYTES (128 * 128)            // 16384
#define STAGE_BYTES (4 * BUF_BYTES)      // 64KB
#define GEMM_SMEM (2 * STAGE_BYTES + 2048)

__device__ __forceinline__ void load_chunk(
    uint32_t stage,
    const __nv_bfloat16* __restrict__ Ah, const __nv_bfloat16* __restrict__ Al,
    const __nv_bfloat16* __restrict__ Bh, const __nv_bfloat16* __restrict__ Bl,
    int m0, int n0, int kc, int t)
{
#pragma unroll
    for (int p = 0; p < 4; p++) {
        int u = t + p * 256;
        int row = u >> 3, seg = u & 7;
        size_t go = (size_t)(m0 + row) * GK + kc + seg * 8;
        uint32_t so = SMEM_SWZ(row * 128 + seg * 16);
        cp_async16(stage + so, Ah + go);
        cp_async16(stage + BUF_BYTES + so, Al + go);
    }
#pragma unroll
    for (int p = 0; p < 4; p++) {
        int u = t + p * 256;
        int row = u >> 3, seg = u & 7;
        size_t go = (size_t)(n0 + row) * GK + kc + seg * 8;
        uint32_t so = SMEM_SWZ(row * 128 + seg * 16);
        cp_async16(stage + 2 * BUF_BYTES + so, Bh + go);
        cp_async16(stage + 3 * BUF_BYTES + so, Bl + go);
    }
}

__global__ __launch_bounds__(256, 1)
void gemm_tc_kernel(
    const __nv_bfloat16* __restrict__ Ah, const __nv_bfloat16* __restrict__ Al,
    const __nv_bfloat16* __restrict__ Bh, const __nv_bfloat16* __restrict__ Bl,
    const float* __restrict__ bias, float* __restrict__ C,
    __nv_bfloat16* __restrict__ Ch, __nv_bfloat16* __restrict__ Cl, float scale)
{
    extern __shared__ char smbuf[];
    const uint32_t tiles = (smem_u32(smbuf) + 1023) & ~1023u;
    const int t = threadIdx.x;
    const int lane = t & 31, wid = t >> 5;
    const int wm = wid & 1, wn = wid >> 1;
    const int n0 = blockIdx.x * BN;
    const int m0 = blockIdx.y * BM;

    const uint32_t stg[2] = { tiles, tiles + STAGE_BYTES };

    const int a_row = lane & 15;
    const int a_k8 = (lane >> 4) * 8;
    const int b_row = (lane & 7) + ((lane >> 4) & 1) * 8;
    const int b_k8 = ((lane >> 3) & 1) * 8;

    float acc[4][4][4];
#pragma unroll
    for (int mt = 0; mt < 4; mt++)
#pragma unroll
        for (int nt = 0; nt < 4; nt++)
#pragma unroll
            for (int q = 0; q < 4; q++) acc[mt][nt][q] = 0.0f;

    load_chunk(stg[0], Ah, Al, Bh, Bl, m0, n0, 0, t);
    cp_commit();

    for (int c = 0; c < NCHUNK; c++) {
        const int s = c & 1;
        cp_wait<0>();
        __syncthreads();
        if (c + 1 < NCHUNK) {
            load_chunk(stg[s ^ 1], Ah, Al, Bh, Bl, m0, n0, (c + 1) * BK, t);
            cp_commit();
        }

        const uint32_t Abase = stg[s];
        const uint32_t Bbase = stg[s] + 2 * BUF_BYTES;
#pragma unroll
        for (int kk = 0; kk < 4; kk++) {
            uint32_t ah[4][4], al[4][4];
#pragma unroll
            for (int mt = 0; mt < 4; mt++) {
                uint32_t off = (uint32_t)(wm * 64 + mt * 16 + a_row) * 128
                             + (kk * 16 + a_k8) * 2;
                uint32_t sw = SMEM_SWZ(off);
                ldmx4(ah[mt], Abase + sw);
                ldmx4(al[mt], Abase + BUF_BYTES + sw);
            }
            uint32_t bh[2][4], bl[2][4];
#pragma unroll
            for (int nb = 0; nb < 2; nb++) {
                uint32_t off = (uint32_t)(wn * 32 + nb * 16 + b_row) * 128
                             + (kk * 16 + b_k8) * 2;
                uint32_t sw = SMEM_SWZ(off);
                ldmx4(bh[nb], Bbase + sw);
                ldmx4(bl[nb], Bbase + BUF_BYTES + sw);
            }
#pragma unroll
            for (int mt = 0; mt < 4; mt++)
#pragma unroll
                for (int nt = 0; nt < 4; nt++) {
                    const uint32_t* fh = &bh[nt >> 1][(nt & 1) * 2];
                    const uint32_t* fl = &bl[nt >> 1][(nt & 1) * 2];
                    mma16816(acc[mt][nt], ah[mt], fh);
                    mma16816(acc[mt][nt], ah[mt], fl);
                    mma16816(acc[mt][nt], al[mt], fh);
                }
        }
        __syncthreads();
    }

    // epilogue
#pragma unroll
    for (int mt = 0; mt < 4; mt++) {
        const int m = m0 + wm * 64 + mt * 16 + (lane >> 2);
#pragma unroll
        for (int nt = 0; nt < 4; nt++) {
            const int n = n0 + wn * 32 + nt * 8 + (lane & 3) * 2;
            const float b0 = bias[n], b1 = bias[n + 1];
            float v00 = (acc[mt][nt][0] + b0) * scale;
            float v01 = (acc[mt][nt][1] + b1) * scale;
            float v10 = (acc[mt][nt][2] + b0) * scale;
            float v11 = (acc[mt][nt][3] + b1) * scale;
            if (Ch) {
                uint32_t h0, l0, h1, l1;
                split2(v00, v01, h0, l0);
                split2(v10, v11, h1, l1);
                *(uint32_t*)(Ch + (size_t)m * GK + n) = h0;
                *(uint32_t*)(Cl + (size_t)m * GK + n) = l0;
                *(uint32_t*)(Ch + (size_t)(m + 8) * GK + n) = h1;
                *(uint32_t*)(Cl + (size_t)(m + 8) * GK + n) = l1;
            } else {
                float2 o0 = { v00, v01 }, o1 = { v10, v11 };
                *(float2*)(C + (size_t)m * GK + n) = o0;
                *(float2*)(C + (size_t)(m + 8) * GK + n) = o1;
            }
        }
    }
}

// ---------------------------------------------------------------------------
// Tensor-core attention: one block per (c, h). 256 threads, 8 warps.
// Warp w owns rows w*16..w*16+15, computes full 128-wide score row.
// SMEM: QH/QL/KH/KL 16KB each (128 rows x 128B, SW128),
//       VT hi/lo in 2 j-halves, 8KB each. Total 96KB.
// ---------------------------------------------------------------------------
#define ATT_SMEM (98304 + 1024)

__global__ __launch_bounds__(256, 2) void attn_kernel(
    const __nv_bfloat16* __restrict__ Qh, const __nv_bfloat16* __restrict__ Ql,
    const __nv_bfloat16* __restrict__ Kh, const __nv_bfloat16* __restrict__ Kl,
    const __nv_bfloat16* __restrict__ Vh, const __nv_bfloat16* __restrict__ Vl,
    const int* __restrict__ mask, float* __restrict__ probs,
    __nv_bfloat16* __restrict__ Ch, __nv_bfloat16* __restrict__ Cl)
{
    extern __shared__ char smraw[];
    const uint32_t smb0 = smem_u32(smraw);
    const uint32_t smb = (smb0 + 1023) & ~1023u;
    char* smc = smraw + (smb - smb0);

    const uint32_t QH = smb, QL = smb + 16384, KH = smb + 32768, KL = smb + 49152;
    const uint32_t VH0 = smb + 65536, VH1 = VH0 + 8192;
    const uint32_t VL0 = smb + 81920, VL1 = VL0 + 8192;

    const int c = blockIdx.x, hh = blockIdx.y;
    const int t = threadIdx.x, lane = t & 31, w = t >> 5;

    // ---- load Q,K (cp.async) and V transposed ----
#pragma unroll
    for (int p = 0; p < 4; p++) {
        int u = t + p * 256;
        int row = u >> 3, seg = u & 7;
        size_t g = ((size_t)row * C_DIM + c) * E_DIM + hh * 64 + seg * 8;
        uint32_t so = SMEM_SWZ(row * 128 + seg * 16);
        cp_async16(QH + so, Qh + g);
        cp_async16(QL + so, Ql + g);
        cp_async16(KH + so, Kh + g);
        cp_async16(KL + so, Kl + g);
    }
    cp_commit();
#pragma unroll
    for (int p = 0; p < 4; p++) {
        int u = t + p * 256;
        int j = u >> 3, seg = u & 7;
        size_t g = ((size_t)j * C_DIM + c) * E_DIM + hh * 64 + seg * 8;
        uint32_t vbh = ((j & 64) ? VH1 : VH0) - smb;
        uint32_t vbl = ((j & 64) ? VL1 : VL0) - smb;
        int jj = (j & 63) * 2;
        uint4 hv = *(const uint4*)(Vh + g);
        uint4 lv = *(const uint4*)(Vl + g);
        const __nv_bfloat16* he = (const __nv_bfloat16*)&hv;
        const __nv_bfloat16* le = (const __nv_bfloat16*)&lv;
#pragma unroll
        for (int e = 0; e < 8; e++) {
            int d = seg * 8 + e;
            uint32_t so = SMEM_SWZ(d * 128 + jj);
            *(__nv_bfloat16*)(smc + vbh + so) = he[e];
            *(__nv_bfloat16*)(smc + vbl + so) = le[e];
        }
    }
    cp_wait<0>();
    __syncthreads();

    // ---- scores: S[i][j], warp-local full rows ----
    const int w16 = w * 16;
    const int a_row = lane & 15, a_k8 = (lane >> 4) * 8;
    const int b_row = (lane & 7) + ((lane >> 4) & 1) * 8, b_k8 = ((lane >> 3) & 1) * 8;

    float S[16][4];
#pragma unroll
    for (int nt = 0; nt < 16; nt++)
#pragma unroll
        for (int q = 0; q < 4; q++) S[nt][q] = 0.0f;

#pragma unroll
    for (int kk = 0; kk < 4; kk++) {
        uint32_t ao = SMEM_SWZ((w16 + a_row) * 128 + (kk * 16 + a_k8) * 2);
        uint32_t ah[4], al[4];
        ldmx4(ah, QH + ao);
        ldmx4(al, QL + ao);
#pragma unroll
        for (int nb = 0; nb < 8; nb++) {
            uint32_t bo = SMEM_SWZ((nb * 16 + b_row) * 128 + (kk * 16 + b_k8) * 2);
            uint32_t bh[4], bl[4];
            ldmx4(bh, KH + bo);
            ldmx4(bl, KL + bo);
            mma16816(S[nb * 2], ah, bh);
            mma16816(S[nb * 2], ah, bl);
            mma16816(S[nb * 2], al, bh);
            mma16816(S[nb * 2 + 1], ah, bh + 2);
            mma16816(S[nb * 2 + 1], ah, bl + 2);
            mma16816(S[nb * 2 + 1], al, bh + 2);
        }
    }

    // ---- mask: padded column -> uniform softmax (exactly matches reference) ----
    if (mask[c] != 0) {
#pragma unroll
        for (int nt = 0; nt < 16; nt++)
#pragma unroll
            for (int q = 0; q < 4; q++) S[nt][q] = 0.0f;
    }

    // ---- register softmax over j (reduce across lane&3 quads) ----
    float mx1 = -1e30f, mx2 = -1e30f;
#pragma unroll
    for (int nt = 0; nt < 16; nt++) {
        mx1 = fmaxf(mx1, fmaxf(S[nt][0], S[nt][1]));
        mx2 = fmaxf(mx2, fmaxf(S[nt][2], S[nt][3]));
    }
    mx1 = fmaxf(mx1, __shfl_xor_sync(0xFFFFFFFF, mx1, 1));
    mx1 = fmaxf(mx1, __shfl_xor_sync(0xFFFFFFFF, mx1, 2));
    mx2 = fmaxf(mx2, __shfl_xor_sync(0xFFFFFFFF, mx2, 1));
    mx2 = fmaxf(mx2, __shfl_xor_sync(0xFFFFFFFF, mx2, 2));

    float s1 = 0.0f, s2 = 0.0f;
#pragma unroll
    for (int nt = 0; nt < 16; nt++) {
        S[nt][0] = __expf(S[nt][0] - mx1); s1 += S[nt][0];
        S[nt][1] = __expf(S[nt][1] - mx1); s1 += S[nt][1];
        S[nt][2] = __expf(S[nt][2] - mx2); s2 += S[nt][2];
        S[nt][3] = __expf(S[nt][3] - mx2); s2 += S[nt][3];
    }
    s1 += __shfl_xor_sync(0xFFFFFFFF, s1, 1);
    s1 += __shfl_xor_sync(0xFFFFFFFF, s1, 2);
    s2 += __shfl_xor_sync(0xFFFFFFFF, s2, 1);
    s2 += __shfl_xor_sync(0xFFFFFFFF, s2, 2);
    const float inv1 = 1.0f / s1, inv2 = 1.0f / s2;
#pragma unroll
    for (int nt = 0; nt < 16; nt++) {
        S[nt][0] *= inv1; S[nt][1] *= inv1;
        S[nt][2] *= inv2; S[nt][3] *= inv2;
    }

    // ---- write attn_probs [h][c][i][j] straight from registers ----
    const int r1 = w16 + (lane >> 2), r2 = r1 + 8;
    const int jb = (lane & 3) * 2;
    {
        float* p1 = probs + ((size_t)hh * C_DIM + c) * 16384 + (size_t)r1 * 128 + jb;
        float* p2 = probs + ((size_t)hh * C_DIM + c) * 16384 + (size_t)r2 * 128 + jb;
#pragma unroll
        for (int nt = 0; nt < 16; nt++) {
            float2 o1 = { S[nt][0], S[nt][1] };
            float2 o2 = { S[nt][2], S[nt][3] };
            *(float2*)(p1 + nt * 8) = o1;
            *(float2*)(p2 + nt * 8) = o2;
        }
    }

    // ---- pack P into hi/lo A-fragments (register-only, FA-style reuse) ----
    uint32_t ph[8][4], pl[8][4];
#pragma unroll
    for (int q = 0; q < 8; q++) {
        const int nt0 = 2 * q, nt1 = 2 * q + 1;
        split2(S[nt0][0], S[nt0][1], ph[q][0], pl[q][0]);
        split2(S[nt0][2], S[nt0][3], ph[q][1], pl[q][1]);
        split2(S[nt1][0], S[nt1][1], ph[q][2], pl[q][2]);
        split2(S[nt1][2], S[nt1][3], ph[q][3], pl[q][3]);
    }

    // ---- context: C[i][d] = sum_j P[i][j] * V[j][d] ----
    float Cc[8][4];
#pragma unroll
    for (int nf = 0; nf < 8; nf++)
#pragma unroll
        for (int q = 0; q < 4; q++) Cc[nf][q] = 0.0f;

#pragma unroll
    for (int q = 0; q < 8; q++) {
        const uint32_t vbh = (q >= 4) ? VH1 : VH0;
        const uint32_t vbl = (q >= 4) ? VL1 : VL0;
        const int ko = (q & 3) * 16;
#pragma unroll
        for (int df = 0; df < 4; df++) {
            uint32_t off = SMEM_SWZ((df * 16 + b_row) * 128 + (ko + b_k8) * 2);
            uint32_t vh[4], vl[4];
            ldmx4(vh, vbh + off);
            ldmx4(vl, vbl + off);
            mma16816(Cc[df * 2], ph[q], vh);
            mma16816(Cc[df * 2], ph[q], vl);
            mma16816(Cc[df * 2], pl[q], vh);
            mma16816(Cc[df * 2 + 1], ph[q], vh + 2);
            mma16816(Cc[df * 2 + 1], ph[q], vl + 2);
            mma16816(Cc[df * 2 + 1], pl[q], vh + 2);
        }
    }

    // ---- write ctx as bf16 hi/lo (fused split) ----
#pragma unroll
    for (int nf = 0; nf < 8; nf++) {
        const int d = nf * 8 + jb;
        size_t o1 = ((size_t)r1 * C_DIM + c) * E_DIM + hh * 64 + d;
        size_t o2 = ((size_t)r2 * C_DIM + c) * E_DIM + hh * 64 + d;
        uint32_t h0, l0, h1, l1;
        split2(Cc[nf][0], Cc[nf][1], h0, l0);
        split2(Cc[nf][2], Cc[nf][3], h1, l1);
        *(uint32_t*)(Ch + o1) = h0;
        *(uint32_t*)(Cl + o1) = l0;
        *(uint32_t*)(Ch + o2) = h1;
        *(uint32_t*)(Cl + o2) = l1;
    }
}

// ---------------------------------------------------------------------------
extern "C" void kernel_launch(void* const* d_in, const int* in_sizes, int n_in,
                              void* d_out, int out_size)
{
    const float* x  = (const float*)d_in[0];
    const int*   mask = (const int*)d_in[1];
    const float* wq = (const float*)d_in[2];
    const float* bq = (const float*)d_in[3];
    const float* wk = (const float*)d_in[4];
    const float* bk = (const float*)d_in[5];
    const float* wv = (const float*)d_in[6];
    const float* bv = (const float*)d_in[7];
    const float* wo = (const float*)d_in[8];
    const float* bo = (const float*)d_in[9];

    float* out   = (float*)d_out;
    float* probs = (float*)d_out + (size_t)M_TOK * E_DIM;

    __nv_bfloat16 *xh, *xl, *qh, *ql, *kh, *kl, *vh, *vl, *ch, *cl, *wh, *wl;
    cudaGetSymbolAddress((void**)&xh, g_xh);
    cudaGetSymbolAddress((void**)&xl, g_xl);
    cudaGetSymbolAddress((void**)&qh, g_qh);
    cudaGetSymbolAddress((void**)&ql, g_ql);
    cudaGetSymbolAddress((void**)&kh, g_kh);
    cudaGetSymbolAddress((void**)&kl, g_kl);
    cudaGetSymbolAddress((void**)&vh, g_vh);
    cudaGetSymbolAddress((void**)&vl, g_vl);
    cudaGetSymbolAddress((void**)&ch, g_ch);
    cudaGetSymbolAddress((void**)&cl, g_cl);
    cudaGetSymbolAddress((void**)&wh, g_wh);
    cudaGetSymbolAddress((void**)&wl, g_wl);

    static bool attr_set = false;
    if (!attr_set) {
        cudaFuncSetAttribute(attn_kernel, cudaFuncAttributeMaxDynamicSharedMemorySize,
                             ATT_SMEM);
        cudaFuncSetAttribute(gemm_tc_kernel, cudaFuncAttributeMaxDynamicSharedMemorySize,
                             GEMM_SMEM);
        attr_set = true;
    }

    const int NW = E_DIM * E_DIM;
    const int NX = M_TOK * E_DIM;

    split_kernel<<<4096, 256>>>(x, xh, xl, NX / 4);
    split_kernel<<<576, 256>>>(wq, wh + 0 * (size_t)NW, wl + 0 * (size_t)NW, NW / 4);
    split_kernel<<<576, 256>>>(wk, wh + 1 * (size_t)NW, wl + 1 * (size_t)NW, NW / 4);
    split_kernel<<<576, 256>>>(wv, wh + 2 * (size_t)NW, wl + 2 * (size_t)NW, NW / 4);
    split_kernel<<<576, 256>>>(wo, wh + 3 * (size_t)NW, wl + 3 * (size_t)NW, NW / 4);

    dim3 gg(E_DIM / BN, M_TOK / BM);    // (6, 256)
    gemm_tc_kernel<<<gg, 256, GEMM_SMEM>>>(xh, xl, wh + 0 * (size_t)NW, wl + 0 * (size_t)NW,
                                           bq, nullptr, qh, ql, SCALING);
    gemm_tc_kernel<<<gg, 256, GEMM_SMEM>>>(xh, xl, wh + 1 * (size_t)NW, wl + 1 * (size_t)NW,
                                           bk, nullptr, kh, kl, 1.0f);
    gemm_tc_kernel<<<gg, 256, GEMM_SMEM>>>(xh, xl, wh + 2 * (size_t)NW, wl + 2 * (size_t)NW,
                                           bv, nullptr, vh, vl, 1.0f);

    dim3 gattn(C_DIM, H_DIM);           // (256, 12)
    attn_kernel<<<gattn, 256, ATT_SMEM>>>(qh, ql, kh, kl, vh, vl, mask, probs, ch, cl);

    gemm_tc_kernel<<<gg, 256, GEMM_SMEM>>>(ch, cl, wh + 3 * (size_t)NW, wl + 3 * (size_t)NW,
                                           bo, out, nullptr, nullptr, 1.0f);
}

// round 6
// speedup vs baseline: 3.1693x; 1.1117x over previous
#include <cuda_runtime.h>
#include <cuda_bf16.h>
#include <cstdint>
#include <math.h>

// Problem constants
#define R_DIM 128
#define C_DIM 256
#define E_DIM 768
#define H_DIM 12
#define D_DIM 64
#define M_TOK (R_DIM * C_DIM)          // 32768
#define SCALING 0.125f

// bf16 hi/lo scratch (device globals; no allocation)
__device__ __align__(128) __nv_bfloat16 g_xh[M_TOK * E_DIM];
__device__ __align__(128) __nv_bfloat16 g_xl[M_TOK * E_DIM];
__device__ __align__(128) __nv_bfloat16 g_qh[M_TOK * E_DIM];
__device__ __align__(128) __nv_bfloat16 g_ql[M_TOK * E_DIM];
__device__ __align__(128) __nv_bfloat16 g_kh[M_TOK * E_DIM];
__device__ __align__(128) __nv_bfloat16 g_kl[M_TOK * E_DIM];
__device__ __align__(128) __nv_bfloat16 g_vh[M_TOK * E_DIM];
__device__ __align__(128) __nv_bfloat16 g_vl[M_TOK * E_DIM];
__device__ __align__(128) __nv_bfloat16 g_ch[M_TOK * E_DIM];
__device__ __align__(128) __nv_bfloat16 g_cl[M_TOK * E_DIM];
__device__ __align__(128) __nv_bfloat16 g_wh[4][E_DIM * E_DIM];
__device__ __align__(128) __nv_bfloat16 g_wl[4][E_DIM * E_DIM];

// ---------------------------------------------------------------------------
// Helpers
// ---------------------------------------------------------------------------
__device__ __forceinline__ uint32_t smem_u32(const void* p) {
    uint32_t a;
    asm("{ .reg .u64 t; cvta.to.shared.u64 t, %1; cvt.u32.u64 %0, t; }" : "=r"(a) : "l"(p));
    return a;
}
__device__ __forceinline__ void cp_async16(uint32_t s, const void* g) {
    size_t ga = __cvta_generic_to_global(g);
    asm volatile("cp.async.cg.shared.global [%0], [%1], 16;" :: "r"(s), "l"(ga));
}
__device__ __forceinline__ void cp_commit() { asm volatile("cp.async.commit_group;" ::: "memory"); }
template <int N> __device__ __forceinline__ void cp_wait() {
    asm volatile("cp.async.wait_group %0;" :: "n"(N) : "memory");
}
__device__ __forceinline__ void ldmx4(uint32_t* r, uint32_t addr) {
    asm volatile("ldmatrix.sync.aligned.m8n8.x4.shared.b16 {%0,%1,%2,%3}, [%4];"
        : "=r"(r[0]), "=r"(r[1]), "=r"(r[2]), "=r"(r[3]) : "r"(addr));
}
__device__ __forceinline__ void mma16816(float* c, const uint32_t* a, const uint32_t* b) {
    asm volatile("mma.sync.aligned.m16n8k16.row.col.f32.bf16.bf16.f32 "
        "{%0,%1,%2,%3}, {%4,%5,%6,%7}, {%8,%9}, {%0,%1,%2,%3};"
        : "+f"(c[0]), "+f"(c[1]), "+f"(c[2]), "+f"(c[3])
        : "r"(a[0]), "r"(a[1]), "r"(a[2]), "r"(a[3]), "r"(b[0]), "r"(b[1]));
}
__device__ __forceinline__ void split2(float f0, float f1, uint32_t& hi, uint32_t& lo) {
    __nv_bfloat16 h0 = __float2bfloat16(f0);
    __nv_bfloat16 h1 = __float2bfloat16(f1);
    __nv_bfloat16 l0 = __float2bfloat16(f0 - __bfloat162float(h0));
    __nv_bfloat16 l1 = __float2bfloat16(f1 - __bfloat162float(h1));
    __nv_bfloat162 hp = { h0, h1 }, lp = { l0, l1 };
    hi = *(uint32_t*)&hp;
    lo = *(uint32_t*)&lp;
}

#define SMEM_SWZ(o) ((o) ^ (((o) >> 3) & 0x70))

// ---------------------------------------------------------------------------
// Split fp32 -> bf16 hi + bf16 lo (x), and batched variant for the 4 weights
// ---------------------------------------------------------------------------
__global__ __launch_bounds__(256) void split_kernel(
    const float* __restrict__ in, __nv_bfloat16* __restrict__ hi,
    __nv_bfloat16* __restrict__ lo, int n4)
{
    for (int i = blockIdx.x * blockDim.x + threadIdx.x; i < n4; i += gridDim.x * blockDim.x) {
        float4 v = ((const float4*)in)[i];
        __nv_bfloat16 h[4], l[4];
        h[0] = __float2bfloat16(v.x); l[0] = __float2bfloat16(v.x - __bfloat162float(h[0]));
        h[1] = __float2bfloat16(v.y); l[1] = __float2bfloat16(v.y - __bfloat162float(h[1]));
        h[2] = __float2bfloat16(v.z); l[2] = __float2bfloat16(v.z - __bfloat162float(h[2]));
        h[3] = __float2bfloat16(v.w); l[3] = __float2bfloat16(v.w - __bfloat162float(h[3]));
        ((uint2*)hi)[i] = *(uint2*)h;
        ((uint2*)lo)[i] = *(uint2*)l;
    }
}

__global__ __launch_bounds__(256) void split4_kernel(
    const float* __restrict__ w0, const float* __restrict__ w1,
    const float* __restrict__ w2, const float* __restrict__ w3,
    __nv_bfloat16* __restrict__ hbase, __nv_bfloat16* __restrict__ lbase, int n4)
{
    const float* src[4] = { w0, w1, w2, w3 };
    const int b = blockIdx.y;
    const float* in = src[b];
    __nv_bfloat16* hi = hbase + (size_t)b * (E_DIM * E_DIM);
    __nv_bfloat16* lo = lbase + (size_t)b * (E_DIM * E_DIM);
    for (int i = blockIdx.x * blockDim.x + threadIdx.x; i < n4; i += gridDim.x * blockDim.x) {
        float4 v = ((const float4*)in)[i];
        __nv_bfloat16 h[4], l[4];
        h[0] = __float2bfloat16(v.x); l[0] = __float2bfloat16(v.x - __bfloat162float(h[0]));
        h[1] = __float2bfloat16(v.y); l[1] = __float2bfloat16(v.y - __bfloat162float(h[1]));
        h[2] = __float2bfloat16(v.z); l[2] = __float2bfloat16(v.z - __bfloat162float(h[2]));
        h[3] = __float2bfloat16(v.w); l[3] = __float2bfloat16(v.w - __bfloat162float(h[3]));
        ((uint2*)hi)[i] = *(uint2*)h;
        ((uint2*)lo)[i] = *(uint2*)l;
    }
}

// ---------------------------------------------------------------------------
// mma.sync GEMM: acc = sum_k A[m,k]*W[n,k]; out = (acc + bias[n]) * scale
// If Ch != nullptr: write bf16 hi/lo split; else write fp32 to C.
// BM=128, BN=64, BK=64. 256 thr, 4(M)x2(N) warps, warp tile 32x32.
// 3 MMA terms: hh + hl + lh. Stage = 48KB, double-buffered -> 2 CTAs/SM.
// ---------------------------------------------------------------------------
#define GK 768
#define BM 128
#define BN 64
#define BK 64
#define NCHUNK (GK / BK)                 // 12
#define ABUF_BYTES (128 * 128)           // 16384
#define BBUF_BYTES (64 * 128)            // 8192
#define STAGE_BYTES (2 * ABUF_BYTES + 2 * BBUF_BYTES)   // 49152
#define GEMM_SMEM (2 * STAGE_BYTES + 1024)

__device__ __forceinline__ void load_chunk(
    uint32_t stage,
    const __nv_bfloat16* __restrict__ Ah, const __nv_bfloat16* __restrict__ Al,
    const __nv_bfloat16* __restrict__ Bh, const __nv_bfloat16* __restrict__ Bl,
    int m0, int n0, int kc, int t)
{
#pragma unroll
    for (int p = 0; p < 4; p++) {               // A: 128 rows x 8 segs of 16B
        int u = t + p * 256;
        int row = u >> 3, seg = u & 7;
        size_t go = (size_t)(m0 + row) * GK + kc + seg * 8;
        uint32_t so = SMEM_SWZ(row * 128 + seg * 16);
        cp_async16(stage + so, Ah + go);
        cp_async16(stage + ABUF_BYTES + so, Al + go);
    }
#pragma unroll
    for (int p = 0; p < 2; p++) {               // B: 64 rows x 8 segs
        int u = t + p * 256;
        int row = u >> 3, seg = u & 7;
        size_t go = (size_t)(n0 + row) * GK + kc + seg * 8;
        uint32_t so = SMEM_SWZ(row * 128 + seg * 16);
        cp_async16(stage + 2 * ABUF_BYTES + so, Bh + go);
        cp_async16(stage + 2 * ABUF_BYTES + BBUF_BYTES + so, Bl + go);
    }
}

__global__ __launch_bounds__(256, 2)
void gemm_tc_kernel(
    const __nv_bfloat16* __restrict__ Ah, const __nv_bfloat16* __restrict__ Al,
    const __nv_bfloat16* __restrict__ Bh, const __nv_bfloat16* __restrict__ Bl,
    const float* __restrict__ bias, float* __restrict__ C,
    __nv_bfloat16* __restrict__ Ch, __nv_bfloat16* __restrict__ Cl, float scale)
{
    extern __shared__ char smbuf[];
    const uint32_t tiles = (smem_u32(smbuf) + 1023) & ~1023u;
    const int t = threadIdx.x;
    const int lane = t & 31, wid = t >> 5;
    const int wm = wid >> 1, wn = wid & 1;      // 4(M) x 2(N)
    const int n0 = blockIdx.x * BN;
    const int m0 = blockIdx.y * BM;

    const uint32_t stg[2] = { tiles, tiles + STAGE_BYTES };

    const int a_row = lane & 15;
    const int a_k8 = (lane >> 4) * 8;
    const int b_row = (lane & 7) + ((lane >> 4) & 1) * 8;
    const int b_k8 = ((lane >> 3) & 1) * 8;

    float acc[2][4][4];
#pragma unroll
    for (int mt = 0; mt < 2; mt++)
#pragma unroll
        for (int nt = 0; nt < 4; nt++)
#pragma unroll
            for (int q = 0; q < 4; q++) acc[mt][nt][q] = 0.0f;

    load_chunk(stg[0], Ah, Al, Bh, Bl, m0, n0, 0, t);
    cp_commit();

    for (int c = 0; c < NCHUNK; c++) {
        const int s = c & 1;
        cp_wait<0>();
        __syncthreads();
        if (c + 1 < NCHUNK) {
            load_chunk(stg[s ^ 1], Ah, Al, Bh, Bl, m0, n0, (c + 1) * BK, t);
            cp_commit();
        }

        const uint32_t Abase = stg[s];
        const uint32_t Bbase = stg[s] + 2 * ABUF_BYTES;
#pragma unroll
        for (int kk = 0; kk < 4; kk++) {
            uint32_t ah[2][4], al[2][4];
#pragma unroll
            for (int mt = 0; mt < 2; mt++) {
                uint32_t off = (uint32_t)(wm * 32 + mt * 16 + a_row) * 128
                             + (kk * 16 + a_k8) * 2;
                uint32_t sw = SMEM_SWZ(off);
                ldmx4(ah[mt], Abase + sw);
                ldmx4(al[mt], Abase + ABUF_BYTES + sw);
            }
            uint32_t bh[2][4], bl[2][4];
#pragma unroll
            for (int nb = 0; nb < 2; nb++) {
                uint32_t off = (uint32_t)(wn * 32 + nb * 16 + b_row) * 128
                             + (kk * 16 + b_k8) * 2;
                uint32_t sw = SMEM_SWZ(off);
                ldmx4(bh[nb], Bbase + sw);
                ldmx4(bl[nb], Bbase + BBUF_BYTES + sw);
            }
#pragma unroll
            for (int mt = 0; mt < 2; mt++)
#pragma unroll
                for (int nt = 0; nt < 4; nt++) {
                    const uint32_t* fh = &bh[nt >> 1][(nt & 1) * 2];
                    const uint32_t* fl = &bl[nt >> 1][(nt & 1) * 2];
                    mma16816(acc[mt][nt], ah[mt], fh);
                    mma16816(acc[mt][nt], ah[mt], fl);
                    mma16816(acc[mt][nt], al[mt], fh);
                }
        }
        __syncthreads();
    }

    // epilogue
#pragma unroll
    for (int mt = 0; mt < 2; mt++) {
        const int m = m0 + wm * 32 + mt * 16 + (lane >> 2);
#pragma unroll
        for (int nt = 0; nt < 4; nt++) {
            const int n = n0 + wn * 32 + nt * 8 + (lane & 3) * 2;
            const float b0 = bias[n], b1 = bias[n + 1];
            float v00 = (acc[mt][nt][0] + b0) * scale;
            float v01 = (acc[mt][nt][1] + b1) * scale;
            float v10 = (acc[mt][nt][2] + b0) * scale;
            float v11 = (acc[mt][nt][3] + b1) * scale;
            if (Ch) {
                uint32_t h0, l0, h1, l1;
                split2(v00, v01, h0, l0);
                split2(v10, v11, h1, l1);
                *(uint32_t*)(Ch + (size_t)m * GK + n) = h0;
                *(uint32_t*)(Cl + (size_t)m * GK + n) = l0;
                *(uint32_t*)(Ch + (size_t)(m + 8) * GK + n) = h1;
                *(uint32_t*)(Cl + (size_t)(m + 8) * GK + n) = l1;
            } else {
                float2 o0 = { v00, v01 }, o1 = { v10, v11 };
                *(float2*)(C + (size_t)m * GK + n) = o0;
                *(float2*)(C + (size_t)(m + 8) * GK + n) = o1;
            }
        }
    }
}

// ---------------------------------------------------------------------------
// Tensor-core attention: one block per (c, h). 256 threads, 8 warps.
// (unchanged from R5 — known good)
// ---------------------------------------------------------------------------
#define ATT_SMEM (98304 + 1024)

__global__ __launch_bounds__(256, 2) void attn_kernel(
    const __nv_bfloat16* __restrict__ Qh, const __nv_bfloat16* __restrict__ Ql,
    const __nv_bfloat16* __restrict__ Kh, const __nv_bfloat16* __restrict__ Kl,
    const __nv_bfloat16* __restrict__ Vh, const __nv_bfloat16* __restrict__ Vl,
    const int* __restrict__ mask, float* __restrict__ probs,
    __nv_bfloat16* __restrict__ Ch, __nv_bfloat16* __restrict__ Cl)
{
    extern __shared__ char smraw[];
    const uint32_t smb0 = smem_u32(smraw);
    const uint32_t smb = (smb0 + 1023) & ~1023u;
    char* smc = smraw + (smb - smb0);

    const uint32_t QH = smb, QL = smb + 16384, KH = smb + 32768, KL = smb + 49152;
    const uint32_t VH0 = smb + 65536, VH1 = VH0 + 8192;
    const uint32_t VL0 = smb + 81920, VL1 = VL0 + 8192;

    const int c = blockIdx.x, hh = blockIdx.y;
    const int t = threadIdx.x, lane = t & 31, w = t >> 5;

#pragma unroll
    for (int p = 0; p < 4; p++) {
        int u = t + p * 256;
        int row = u >> 3, seg = u & 7;
        size_t g = ((size_t)row * C_DIM + c) * E_DIM + hh * 64 + seg * 8;
        uint32_t so = SMEM_SWZ(row * 128 + seg * 16);
        cp_async16(QH + so, Qh + g);
        cp_async16(QL + so, Ql + g);
        cp_async16(KH + so, Kh + g);
        cp_async16(KL + so, Kl + g);
    }
    cp_commit();
#pragma unroll
    for (int p = 0; p < 4; p++) {
        int u = t + p * 256;
        int j = u >> 3, seg = u & 7;
        size_t g = ((size_t)j * C_DIM + c) * E_DIM + hh * 64 + seg * 8;
        uint32_t vbh = ((j & 64) ? VH1 : VH0) - smb;
        uint32_t vbl = ((j & 64) ? VL1 : VL0) - smb;
        int jj = (j & 63) * 2;
        uint4 hv = *(const uint4*)(Vh + g);
        uint4 lv = *(const uint4*)(Vl + g);
        const __nv_bfloat16* he = (const __nv_bfloat16*)&hv;
        const __nv_bfloat16* le = (const __nv_bfloat16*)&lv;
#pragma unroll
        for (int e = 0; e < 8; e++) {
            int d = seg * 8 + e;
            uint32_t so = SMEM_SWZ(d * 128 + jj);
            *(__nv_bfloat16*)(smc + vbh + so) = he[e];
            *(__nv_bfloat16*)(smc + vbl + so) = le[e];
        }
    }
    cp_wait<0>();
    __syncthreads();

    const int w16 = w * 16;
    const int a_row = lane & 15, a_k8 = (lane >> 4) * 8;
    const int b_row = (lane & 7) + ((lane >> 4) & 1) * 8, b_k8 = ((lane >> 3) & 1) * 8;

    float S[16][4];
#pragma unroll
    for (int nt = 0; nt < 16; nt++)
#pragma unroll
        for (int q = 0; q < 4; q++) S[nt][q] = 0.0f;

#pragma unroll
    for (int kk = 0; kk < 4; kk++) {
        uint32_t ao = SMEM_SWZ((w16 + a_row) * 128 + (kk * 16 + a_k8) * 2);
        uint32_t ah[4], al[4];
        ldmx4(ah, QH + ao);
        ldmx4(al, QL + ao);
#pragma unroll
        for (int nb = 0; nb < 8; nb++) {
            uint32_t bo = SMEM_SWZ((nb * 16 + b_row) * 128 + (kk * 16 + b_k8) * 2);
            uint32_t bh[4], bl[4];
            ldmx4(bh, KH + bo);
            ldmx4(bl, KL + bo);
            mma16816(S[nb * 2], ah, bh);
            mma16816(S[nb * 2], ah, bl);
            mma16816(S[nb * 2], al, bh);
            mma16816(S[nb * 2 + 1], ah, bh + 2);
            mma16816(S[nb * 2 + 1], ah, bl + 2);
            mma16816(S[nb * 2 + 1], al, bh + 2);
        }
    }

    if (mask[c] != 0) {
#pragma unroll
        for (int nt = 0; nt < 16; nt++)
#pragma unroll
            for (int q = 0; q < 4; q++) S[nt][q] = 0.0f;
    }

    float mx1 = -1e30f, mx2 = -1e30f;
#pragma unroll
    for (int nt = 0; nt < 16; nt++) {
        mx1 = fmaxf(mx1, fmaxf(S[nt][0], S[nt][1]));
        mx2 = fmaxf(mx2, fmaxf(S[nt][2], S[nt][3]));
    }
    mx1 = fmaxf(mx1, __shfl_xor_sync(0xFFFFFFFF, mx1, 1));
    mx1 = fmaxf(mx1, __shfl_xor_sync(0xFFFFFFFF, mx1, 2));
    mx2 = fmaxf(mx2, __shfl_xor_sync(0xFFFFFFFF, mx2, 1));
    mx2 = fmaxf(mx2, __shfl_xor_sync(0xFFFFFFFF, mx2, 2));

    float s1 = 0.0f, s2 = 0.0f;
#pragma unroll
    for (int nt = 0; nt < 16; nt++) {
        S[nt][0] = __expf(S[nt][0] - mx1); s1 += S[nt][0];
        S[nt][1] = __expf(S[nt][1] - mx1); s1 += S[nt][1];
        S[nt][2] = __expf(S[nt][2] - mx2); s2 += S[nt][2];
        S[nt][3] = __expf(S[nt][3] - mx2); s2 += S[nt][3];
    }
    s1 += __shfl_xor_sync(0xFFFFFFFF, s1, 1);
    s1 += __shfl_xor_sync(0xFFFFFFFF, s1, 2);
    s2 += __shfl_xor_sync(0xFFFFFFFF, s2, 1);
    s2 += __shfl_xor_sync(0xFFFFFFFF, s2, 2);
    const float inv1 = 1.0f / s1, inv2 = 1.0f / s2;
#pragma unroll
    for (int nt = 0; nt < 16; nt++) {
        S[nt][0] *= inv1; S[nt][1] *= inv1;
        S[nt][2] *= inv2; S[nt][3] *= inv2;
    }

    const int r1 = w16 + (lane >> 2), r2 = r1 + 8;
    const int jb = (lane & 3) * 2;
    {
        float* p1 = probs + ((size_t)hh * C_DIM + c) * 16384 + (size_t)r1 * 128 + jb;
        float* p2 = probs + ((size_t)hh * C_DIM + c) * 16384 + (size_t)r2 * 128 + jb;
#pragma unroll
        for (int nt = 0; nt < 16; nt++) {
            float2 o1 = { S[nt][0], S[nt][1] };
            float2 o2 = { S[nt][2], S[nt][3] };
            *(float2*)(p1 + nt * 8) = o1;
            *(float2*)(p2 + nt * 8) = o2;
        }
    }

    uint32_t ph[8][4], pl[8][4];
#pragma unroll
    for (int q = 0; q < 8; q++) {
        const int nt0 = 2 * q, nt1 = 2 * q + 1;
        split2(S[nt0][0], S[nt0][1], ph[q][0], pl[q][0]);
        split2(S[nt0][2], S[nt0][3], ph[q][1], pl[q][1]);
        split2(S[nt1][0], S[nt1][1], ph[q][2], pl[q][2]);
        split2(S[nt1][2], S[nt1][3], ph[q][3], pl[q][3]);
    }

    float Cc[8][4];
#pragma unroll
    for (int nf = 0; nf < 8; nf++)
#pragma unroll
        for (int q = 0; q < 4; q++) Cc[nf][q] = 0.0f;

#pragma unroll
    for (int q = 0; q < 8; q++) {
        const uint32_t vbh = (q >= 4) ? VH1 : VH0;
        const uint32_t vbl = (q >= 4) ? VL1 : VL0;
        const int ko = (q & 3) * 16;
#pragma unroll
        for (int df = 0; df < 4; df++) {
            uint32_t off = SMEM_SWZ((df * 16 + b_row) * 128 + (ko + b_k8) * 2);
            uint32_t vh[4], vl[4];
            ldmx4(vh, vbh + off);
            ldmx4(vl, vbl + off);
            mma16816(Cc[df * 2], ph[q], vh);
            mma16816(Cc[df * 2], ph[q], vl);
            mma16816(Cc[df * 2], pl[q], vh);
            mma16816(Cc[df * 2 + 1], ph[q], vh + 2);
            mma16816(Cc[df * 2 + 1], ph[q], vl + 2);
            mma16816(Cc[df * 2 + 1], pl[q], vh + 2);
        }
    }

#pragma unroll
    for (int nf = 0; nf < 8; nf++) {
        const int d = nf * 8 + jb;
        size_t o1 = ((size_t)r1 * C_DIM + c) * E_DIM + hh * 64 + d;
        size_t o2 = ((size_t)r2 * C_DIM + c) * E_DIM + hh * 64 + d;
        uint32_t h0, l0, h1, l1;
        split2(Cc[nf][0], Cc[nf][1], h0, l0);
        split2(Cc[nf][2], Cc[nf][3], h1, l1);
        *(uint32_t*)(Ch + o1) = h0;
        *(uint32_t*)(Cl + o1) = l0;
        *(uint32_t*)(Ch + o2) = h1;
        *(uint32_t*)(Cl + o2) = l1;
    }
}

// ---------------------------------------------------------------------------
extern "C" void kernel_launch(void* const* d_in, const int* in_sizes, int n_in,
                              void* d_out, int out_size)
{
    const float* x  = (const float*)d_in[0];
    const int*   mask = (const int*)d_in[1];
    const float* wq = (const float*)d_in[2];
    const float* bq = (const float*)d_in[3];
    const float* wk = (const float*)d_in[4];
    const float* bk = (const float*)d_in[5];
    const float* wv = (const float*)d_in[6];
    const float* bv = (const float*)d_in[7];
    const float* wo = (const float*)d_in[8];
    const float* bo = (const float*)d_in[9];

    float* out   = (float*)d_out;
    float* probs = (float*)d_out + (size_t)M_TOK * E_DIM;

    __nv_bfloat16 *xh, *xl, *qh, *ql, *kh, *kl, *vh, *vl, *ch, *cl, *wh, *wl;
    cudaGetSymbolAddress((void**)&xh, g_xh);
    cudaGetSymbolAddress((void**)&xl, g_xl);
    cudaGetSymbolAddress((void**)&qh, g_qh);
    cudaGetSymbolAddress((void**)&ql, g_ql);
    cudaGetSymbolAddress((void**)&kh, g_kh);
    cudaGetSymbolAddress((void**)&kl, g_kl);
    cudaGetSymbolAddress((void**)&vh, g_vh);
    cudaGetSymbolAddress((void**)&vl, g_vl);
    cudaGetSymbolAddress((void**)&ch, g_ch);
    cudaGetSymbolAddress((void**)&cl, g_cl);
    cudaGetSymbolAddress((void**)&wh, g_wh);
    cudaGetSymbolAddress((void**)&wl, g_wl);

    static bool attr_set = false;
    if (!attr_set) {
        cudaFuncSetAttribute(attn_kernel, cudaFuncAttributeMaxDynamicSharedMemorySize,
                             ATT_SMEM);
        cudaFuncSetAttribute(gemm_tc_kernel, cudaFuncAttributeMaxDynamicSharedMemorySize,
                             GEMM_SMEM);
        attr_set = true;
    }

    const int NW = E_DIM * E_DIM;
    const int NX = M_TOK * E_DIM;

    split_kernel<<<4096, 256>>>(x, xh, xl, NX / 4);
    split4_kernel<<<dim3(144, 4), 256>>>(wq, wk, wv, wo, wh, wl, NW / 4);

    dim3 gg(E_DIM / BN, M_TOK / BM);    // (12, 256)
    gemm_tc_kernel<<<gg, 256, GEMM_SMEM>>>(xh, xl, wh + 0 * (size_t)NW, wl + 0 * (size_t)NW,
                                           bq, nullptr, qh, ql, SCALING);
    gemm_tc_kernel<<<gg, 256, GEMM_SMEM>>>(xh, xl, wh + 1 * (size_t)NW, wl + 1 * (size_t)NW,
                                           bk, nullptr, kh, kl, 1.0f);
    gemm_tc_kernel<<<gg, 256, GEMM_SMEM>>>(xh, xl, wh + 2 * (size_t)NW, wl + 2 * (size_t)NW,
                                           bv, nullptr, vh, vl, 1.0f);

    dim3 gattn(C_DIM, H_DIM);           // (256, 12)
    attn_kernel<<<gattn, 256, ATT_SMEM>>>(qh, ql, kh, kl, vh, vl, mask, probs, ch, cl);

    gemm_tc_kernel<<<gg, 256, GEMM_SMEM>>>(ch, cl, wh + 3 * (size_t)NW, wl + 3 * (size_t)NW,
                                           bo, out, nullptr, nullptr, 1.0f);
}

// round 7
// speedup vs baseline: 3.3491x; 1.0567x over previous
#include <cuda_runtime.h>
#include <cuda_bf16.h>
#include <cstdint>
#include <math.h>

// Problem constants
#define R_DIM 128
#define C_DIM 256
#define E_DIM 768
#define H_DIM 12
#define D_DIM 64
#define M_TOK (R_DIM * C_DIM)          // 32768
#define SCALING 0.125f
#define NW_ELEM (E_DIM * E_DIM)

// bf16 hi/lo scratch (device globals; no allocation)
__device__ __align__(128) __nv_bfloat16 g_xh[M_TOK * E_DIM];
__device__ __align__(128) __nv_bfloat16 g_xl[M_TOK * E_DIM];
__device__ __align__(128) __nv_bfloat16 g_qh[M_TOK * E_DIM];
__device__ __align__(128) __nv_bfloat16 g_ql[M_TOK * E_DIM];
__device__ __align__(128) __nv_bfloat16 g_kh[M_TOK * E_DIM];
__device__ __align__(128) __nv_bfloat16 g_kl[M_TOK * E_DIM];
__device__ __align__(128) __nv_bfloat16 g_vh[M_TOK * E_DIM];
__device__ __align__(128) __nv_bfloat16 g_vl[M_TOK * E_DIM];
__device__ __align__(128) __nv_bfloat16 g_ch[M_TOK * E_DIM];
__device__ __align__(128) __nv_bfloat16 g_cl[M_TOK * E_DIM];
__device__ __align__(128) __nv_bfloat16 g_wh[4][NW_ELEM];
__device__ __align__(128) __nv_bfloat16 g_wl[4][NW_ELEM];

// ---------------------------------------------------------------------------
// Helpers
// ---------------------------------------------------------------------------
__device__ __forceinline__ uint32_t smem_u32(const void* p) {
    uint32_t a;
    asm("{ .reg .u64 t; cvta.to.shared.u64 t, %1; cvt.u32.u64 %0, t; }" : "=r"(a) : "l"(p));
    return a;
}
__device__ __forceinline__ void cp_async16(uint32_t s, const void* g) {
    size_t ga = __cvta_generic_to_global(g);
    asm volatile("cp.async.cg.shared.global [%0], [%1], 16;" :: "r"(s), "l"(ga));
}
__device__ __forceinline__ void cp_commit() { asm volatile("cp.async.commit_group;" ::: "memory"); }
template <int N> __device__ __forceinline__ void cp_wait() {
    asm volatile("cp.async.wait_group %0;" :: "n"(N) : "memory");
}
__device__ __forceinline__ void ldmx4(uint32_t* r, uint32_t addr) {
    asm volatile("ldmatrix.sync.aligned.m8n8.x4.shared.b16 {%0,%1,%2,%3}, [%4];"
        : "=r"(r[0]), "=r"(r[1]), "=r"(r[2]), "=r"(r[3]) : "r"(addr));
}
__device__ __forceinline__ void mma16816(float* c, const uint32_t* a, const uint32_t* b) {
    asm volatile("mma.sync.aligned.m16n8k16.row.col.f32.bf16.bf16.f32 "
        "{%0,%1,%2,%3}, {%4,%5,%6,%7}, {%8,%9}, {%0,%1,%2,%3};"
        : "+f"(c[0]), "+f"(c[1]), "+f"(c[2]), "+f"(c[3])
        : "r"(a[0]), "r"(a[1]), "r"(a[2]), "r"(a[3]), "r"(b[0]), "r"(b[1]));
}
__device__ __forceinline__ void split2(float f0, float f1, uint32_t& hi, uint32_t& lo) {
    __nv_bfloat16 h0 = __float2bfloat16(f0);
    __nv_bfloat16 h1 = __float2bfloat16(f1);
    __nv_bfloat16 l0 = __float2bfloat16(f0 - __bfloat162float(h0));
    __nv_bfloat16 l1 = __float2bfloat16(f1 - __bfloat162float(h1));
    __nv_bfloat162 hp = { h0, h1 }, lp = { l0, l1 };
    hi = *(uint32_t*)&hp;
    lo = *(uint32_t*)&lp;
}

#define SMEM_SWZ(o) ((o) ^ (((o) >> 3) & 0x70))

// ---------------------------------------------------------------------------
// Split fp32 -> bf16 hi + bf16 lo (x), and batched variant for the 4 weights
// ---------------------------------------------------------------------------
__global__ __launch_bounds__(256) void split_kernel(
    const float* __restrict__ in, __nv_bfloat16* __restrict__ hi,
    __nv_bfloat16* __restrict__ lo, int n4)
{
    for (int i = blockIdx.x * blockDim.x + threadIdx.x; i < n4; i += gridDim.x * blockDim.x) {
        float4 v = ((const float4*)in)[i];
        __nv_bfloat16 h[4], l[4];
        h[0] = __float2bfloat16(v.x); l[0] = __float2bfloat16(v.x - __bfloat162float(h[0]));
        h[1] = __float2bfloat16(v.y); l[1] = __float2bfloat16(v.y - __bfloat162float(h[1]));
        h[2] = __float2bfloat16(v.z); l[2] = __float2bfloat16(v.z - __bfloat162float(h[2]));
        h[3] = __float2bfloat16(v.w); l[3] = __float2bfloat16(v.w - __bfloat162float(h[3]));
        ((uint2*)hi)[i] = *(uint2*)h;
        ((uint2*)lo)[i] = *(uint2*)l;
    }
}

__global__ __launch_bounds__(256) void split4_kernel(
    const float* __restrict__ w0, const float* __restrict__ w1,
    const float* __restrict__ w2, const float* __restrict__ w3,
    __nv_bfloat16* __restrict__ hbase, __nv_bfloat16* __restrict__ lbase, int n4)
{
    const float* src[4] = { w0, w1, w2, w3 };
    const int b = blockIdx.y;
    const float* in = src[b];
    __nv_bfloat16* hi = hbase + (size_t)b * NW_ELEM;
    __nv_bfloat16* lo = lbase + (size_t)b * NW_ELEM;
    for (int i = blockIdx.x * blockDim.x + threadIdx.x; i < n4; i += gridDim.x * blockDim.x) {
        float4 v = ((const float4*)in)[i];
        __nv_bfloat16 h[4], l[4];
        h[0] = __float2bfloat16(v.x); l[0] = __float2bfloat16(v.x - __bfloat162float(h[0]));
        h[1] = __float2bfloat16(v.y); l[1] = __float2bfloat16(v.y - __bfloat162float(h[1]));
        h[2] = __float2bfloat16(v.z); l[2] = __float2bfloat16(v.z - __bfloat162float(h[2]));
        h[3] = __float2bfloat16(v.w); l[3] = __float2bfloat16(v.w - __bfloat162float(h[3]));
        ((uint2*)hi)[i] = *(uint2*)h;
        ((uint2*)lo)[i] = *(uint2*)l;
    }
}

// ---------------------------------------------------------------------------
// mma.sync GEMM body: acc = sum_k A[m,k]*W[n,k]; out = (acc + bias[n]) * scale
// BM=128, BN=64, BK=64. 256 thr, 4(M)x2(N) warps, warp tile 32x32.
// 3 MMA terms: hh + hl + lh. Stage = 48KB, double-buffered -> 2 CTAs/SM.
// ---------------------------------------------------------------------------
#define GK 768
#define BM 128
#define BN 64
#define BK 64
#define NCHUNK (GK / BK)                 // 12
#define ABUF_BYTES (128 * 128)           // 16384
#define BBUF_BYTES (64 * 128)            // 8192
#define STAGE_BYTES (2 * ABUF_BYTES + 2 * BBUF_BYTES)   // 49152
#define GEMM_SMEM (2 * STAGE_BYTES + 1024)

__device__ __forceinline__ void load_chunk(
    uint32_t stage,
    const __nv_bfloat16* __restrict__ Ah, const __nv_bfloat16* __restrict__ Al,
    const __nv_bfloat16* __restrict__ Bh, const __nv_bfloat16* __restrict__ Bl,
    int m0, int n0, int kc, int t)
{
#pragma unroll
    for (int p = 0; p < 4; p++) {               // A: 128 rows x 8 segs of 16B
        int u = t + p * 256;
        int row = u >> 3, seg = u & 7;
        size_t go = (size_t)(m0 + row) * GK + kc + seg * 8;
        uint32_t so = SMEM_SWZ(row * 128 + seg * 16);
        cp_async16(stage + so, Ah + go);
        cp_async16(stage + ABUF_BYTES + so, Al + go);
    }
#pragma unroll
    for (int p = 0; p < 2; p++) {               // B: 64 rows x 8 segs
        int u = t + p * 256;
        int row = u >> 3, seg = u & 7;
        size_t go = (size_t)(n0 + row) * GK + kc + seg * 8;
        uint32_t so = SMEM_SWZ(row * 128 + seg * 16);
        cp_async16(stage + 2 * ABUF_BYTES + so, Bh + go);
        cp_async16(stage + 2 * ABUF_BYTES + BBUF_BYTES + so, Bl + go);
    }
}

template <bool SPLIT_OUT>
__device__ __forceinline__ void gemm_body(
    const __nv_bfloat16* __restrict__ Ah, const __nv_bfloat16* __restrict__ Al,
    const __nv_bfloat16* __restrict__ Bh, const __nv_bfloat16* __restrict__ Bl,
    const float* __restrict__ bias, float* __restrict__ C,
    __nv_bfloat16* __restrict__ Ch, __nv_bfloat16* __restrict__ Cl,
    float scale, int m0, int n0)
{
    extern __shared__ char smbuf[];
    const uint32_t tiles = (smem_u32(smbuf) + 1023) & ~1023u;
    const int t = threadIdx.x;
    const int lane = t & 31, wid = t >> 5;
    const int wm = wid >> 1, wn = wid & 1;      // 4(M) x 2(N)

    const uint32_t stg[2] = { tiles, tiles + STAGE_BYTES };

    const int a_row = lane & 15;
    const int a_k8 = (lane >> 4) * 8;
    const int b_row = (lane & 7) + ((lane >> 4) & 1) * 8;
    const int b_k8 = ((lane >> 3) & 1) * 8;

    float acc[2][4][4];
#pragma unroll
    for (int mt = 0; mt < 2; mt++)
#pragma unroll
        for (int nt = 0; nt < 4; nt++)
#pragma unroll
            for (int q = 0; q < 4; q++) acc[mt][nt][q] = 0.0f;

    load_chunk(stg[0], Ah, Al, Bh, Bl, m0, n0, 0, t);
    cp_commit();

    for (int c = 0; c < NCHUNK; c++) {
        const int s = c & 1;
        cp_wait<0>();
        __syncthreads();    // orders: reads of stage s (iter c-2.. via program order)
                            // before this iteration's prefetch writes stage s^1;
                            // also makes chunk-c data visible to all warps.
        if (c + 1 < NCHUNK) {
            load_chunk(stg[s ^ 1], Ah, Al, Bh, Bl, m0, n0, (c + 1) * BK, t);
            cp_commit();
        }

        const uint32_t Abase = stg[s];
        const uint32_t Bbase = stg[s] + 2 * ABUF_BYTES;
#pragma unroll
        for (int kk = 0; kk < 4; kk++) {
            uint32_t ah[2][4], al[2][4];
#pragma unroll
            for (int mt = 0; mt < 2; mt++) {
                uint32_t off = (uint32_t)(wm * 32 + mt * 16 + a_row) * 128
                             + (kk * 16 + a_k8) * 2;
                uint32_t sw = SMEM_SWZ(off);
                ldmx4(ah[mt], Abase + sw);
                ldmx4(al[mt], Abase + ABUF_BYTES + sw);
            }
            uint32_t bh[2][4], bl[2][4];
#pragma unroll
            for (int nb = 0; nb < 2; nb++) {
                uint32_t off = (uint32_t)(wn * 32 + nb * 16 + b_row) * 128
                             + (kk * 16 + b_k8) * 2;
                uint32_t sw = SMEM_SWZ(off);
                ldmx4(bh[nb], Bbase + sw);
                ldmx4(bl[nb], Bbase + BBUF_BYTES + sw);
            }
#pragma unroll
            for (int mt = 0; mt < 2; mt++)
#pragma unroll
                for (int nt = 0; nt < 4; nt++) {
                    const uint32_t* fh = &bh[nt >> 1][(nt & 1) * 2];
                    const uint32_t* fl = &bl[nt >> 1][(nt & 1) * 2];
                    mma16816(acc[mt][nt], ah[mt], fh);
                    mma16816(acc[mt][nt], ah[mt], fl);
                    mma16816(acc[mt][nt], al[mt], fh);
                }
        }
        // no trailing barrier: next iteration's top barrier provides the ordering
    }

    // epilogue
#pragma unroll
    for (int mt = 0; mt < 2; mt++) {
        const int m = m0 + wm * 32 + mt * 16 + (lane >> 2);
#pragma unroll
        for (int nt = 0; nt < 4; nt++) {
            const int n = n0 + wn * 32 + nt * 8 + (lane & 3) * 2;
            const float b0 = bias[n], b1 = bias[n + 1];
            float v00 = (acc[mt][nt][0] + b0) * scale;
            float v01 = (acc[mt][nt][1] + b1) * scale;
            float v10 = (acc[mt][nt][2] + b0) * scale;
            float v11 = (acc[mt][nt][3] + b1) * scale;
            if (SPLIT_OUT) {
                uint32_t h0, l0, h1, l1;
                split2(v00, v01, h0, l0);
                split2(v10, v11, h1, l1);
                *(uint32_t*)(Ch + (size_t)m * GK + n) = h0;
                *(uint32_t*)(Cl + (size_t)m * GK + n) = l0;
                *(uint32_t*)(Ch + (size_t)(m + 8) * GK + n) = h1;
                *(uint32_t*)(Cl + (size_t)(m + 8) * GK + n) = l1;
            } else {
                float2 o0 = { v00, v01 }, o1 = { v10, v11 };
                *(float2*)(C + (size_t)m * GK + n) = o0;
                *(float2*)(C + (size_t)(m + 8) * GK + n) = o1;
            }
        }
    }
}

// Merged Q/K/V projection: grid.z selects weight/bias/output/scale.
__global__ __launch_bounds__(256, 2)
void gemm_qkv_kernel(
    const __nv_bfloat16* __restrict__ Ah, const __nv_bfloat16* __restrict__ Al,
    const __nv_bfloat16* __restrict__ whb, const __nv_bfloat16* __restrict__ wlb,
    const float* __restrict__ bq, const float* __restrict__ bk, const float* __restrict__ bv,
    __nv_bfloat16* __restrict__ qh, __nv_bfloat16* __restrict__ ql,
    __nv_bfloat16* __restrict__ kh, __nv_bfloat16* __restrict__ kl,
    __nv_bfloat16* __restrict__ vh, __nv_bfloat16* __restrict__ vl)
{
    const int z = blockIdx.z;
    const __nv_bfloat16* Bh = whb + (size_t)z * NW_ELEM;
    const __nv_bfloat16* Bl = wlb + (size_t)z * NW_ELEM;
    const float* bias = (z == 0) ? bq : (z == 1) ? bk : bv;
    __nv_bfloat16* Ch = (z == 0) ? qh : (z == 1) ? kh : vh;
    __nv_bfloat16* Cl = (z == 0) ? ql : (z == 1) ? kl : vl;
    const float scale = (z == 0) ? SCALING : 1.0f;
    gemm_body<true>(Ah, Al, Bh, Bl, bias, nullptr, Ch, Cl, scale,
                    blockIdx.y * BM, blockIdx.x * BN);
}

// Output projection: fp32 result.
__global__ __launch_bounds__(256, 2)
void gemm_out_kernel(
    const __nv_bfloat16* __restrict__ Ah, const __nv_bfloat16* __restrict__ Al,
    const __nv_bfloat16* __restrict__ Bh, const __nv_bfloat16* __restrict__ Bl,
    const float* __restrict__ bias, float* __restrict__ C)
{
    gemm_body<false>(Ah, Al, Bh, Bl, bias, C, nullptr, nullptr, 1.0f,
                     blockIdx.y * BM, blockIdx.x * BN);
}

// ---------------------------------------------------------------------------
// Tensor-core attention: one block per (c, h). 256 threads, 8 warps.
// (unchanged — known good)
// ---------------------------------------------------------------------------
#define ATT_SMEM (98304 + 1024)

__global__ __launch_bounds__(256, 2) void attn_kernel(
    const __nv_bfloat16* __restrict__ Qh, const __nv_bfloat16* __restrict__ Ql,
    const __nv_bfloat16* __restrict__ Kh, const __nv_bfloat16* __restrict__ Kl,
    const __nv_bfloat16* __restrict__ Vh, const __nv_bfloat16* __restrict__ Vl,
    const int* __restrict__ mask, float* __restrict__ probs,
    __nv_bfloat16* __restrict__ Ch, __nv_bfloat16* __restrict__ Cl)
{
    extern __shared__ char smraw[];
    const uint32_t smb0 = smem_u32(smraw);
    const uint32_t smb = (smb0 + 1023) & ~1023u;
    char* smc = smraw + (smb - smb0);

    const uint32_t QH = smb, QL = smb + 16384, KH = smb + 32768, KL = smb + 49152;
    const uint32_t VH0 = smb + 65536, VH1 = VH0 + 8192;
    const uint32_t VL0 = smb + 81920, VL1 = VL0 + 8192;

    const int c = blockIdx.x, hh = blockIdx.y;
    const int t = threadIdx.x, lane = t & 31, w = t >> 5;

#pragma unroll
    for (int p = 0; p < 4; p++) {
        int u = t + p * 256;
        int row = u >> 3, seg = u & 7;
        size_t g = ((size_t)row * C_DIM + c) * E_DIM + hh * 64 + seg * 8;
        uint32_t so = SMEM_SWZ(row * 128 + seg * 16);
        cp_async16(QH + so, Qh + g);
        cp_async16(QL + so, Ql + g);
        cp_async16(KH + so, Kh + g);
        cp_async16(KL + so, Kl + g);
    }
    cp_commit();
#pragma unroll
    for (int p = 0; p < 4; p++) {
        int u = t + p * 256;
        int j = u >> 3, seg = u & 7;
        size_t g = ((size_t)j * C_DIM + c) * E_DIM + hh * 64 + seg * 8;
        uint32_t vbh = ((j & 64) ? VH1 : VH0) - smb;
        uint32_t vbl = ((j & 64) ? VL1 : VL0) - smb;
        int jj = (j & 63) * 2;
        uint4 hv = *(const uint4*)(Vh + g);
        uint4 lv = *(const uint4*)(Vl + g);
        const __nv_bfloat16* he = (const __nv_bfloat16*)&hv;
        const __nv_bfloat16* le = (const __nv_bfloat16*)&lv;
#pragma unroll
        for (int e = 0; e < 8; e++) {
            int d = seg * 8 + e;
            uint32_t so = SMEM_SWZ(d * 128 + jj);
            *(__nv_bfloat16*)(smc + vbh + so) = he[e];
            *(__nv_bfloat16*)(smc + vbl + so) = le[e];
        }
    }
    cp_wait<0>();
    __syncthreads();

    const int w16 = w * 16;
    const int a_row = lane & 15, a_k8 = (lane >> 4) * 8;
    const int b_row = (lane & 7) + ((lane >> 4) & 1) * 8, b_k8 = ((lane >> 3) & 1) * 8;

    float S[16][4];
#pragma unroll
    for (int nt = 0; nt < 16; nt++)
#pragma unroll
        for (int q = 0; q < 4; q++) S[nt][q] = 0.0f;

#pragma unroll
    for (int kk = 0; kk < 4; kk++) {
        uint32_t ao = SMEM_SWZ((w16 + a_row) * 128 + (kk * 16 + a_k8) * 2);
        uint32_t ah[4], al[4];
        ldmx4(ah, QH + ao);
        ldmx4(al, QL + ao);
#pragma unroll
        for (int nb = 0; nb < 8; nb++) {
            uint32_t bo = SMEM_SWZ((nb * 16 + b_row) * 128 + (kk * 16 + b_k8) * 2);
            uint32_t bh[4], bl[4];
            ldmx4(bh, KH + bo);
            ldmx4(bl, KL + bo);
            mma16816(S[nb * 2], ah, bh);
            mma16816(S[nb * 2], ah, bl);
            mma16816(S[nb * 2], al, bh);
            mma16816(S[nb * 2 + 1], ah, bh + 2);
            mma16816(S[nb * 2 + 1], ah, bl + 2);
            mma16816(S[nb * 2 + 1], al, bh + 2);
        }
    }

    if (mask[c] != 0) {
#pragma unroll
        for (int nt = 0; nt < 16; nt++)
#pragma unroll
            for (int q = 0; q < 4; q++) S[nt][q] = 0.0f;
    }

    float mx1 = -1e30f, mx2 = -1e30f;
#pragma unroll
    for (int nt = 0; nt < 16; nt++) {
        mx1 = fmaxf(mx1, fmaxf(S[nt][0], S[nt][1]));
        mx2 = fmaxf(mx2, fmaxf(S[nt][2], S[nt][3]));
    }
    mx1 = fmaxf(mx1, __shfl_xor_sync(0xFFFFFFFF, mx1, 1));
    mx1 = fmaxf(mx1, __shfl_xor_sync(0xFFFFFFFF, mx1, 2));
    mx2 = fmaxf(mx2, __shfl_xor_sync(0xFFFFFFFF, mx2, 1));
    mx2 = fmaxf(mx2, __shfl_xor_sync(0xFFFFFFFF, mx2, 2));

    float s1 = 0.0f, s2 = 0.0f;
#pragma unroll
    for (int nt = 0; nt < 16; nt++) {
        S[nt][0] = __expf(S[nt][0] - mx1); s1 += S[nt][0];
        S[nt][1] = __expf(S[nt][1] - mx1); s1 += S[nt][1];
        S[nt][2] = __expf(S[nt][2] - mx2); s2 += S[nt][2];
        S[nt][3] = __expf(S[nt][3] - mx2); s2 += S[nt][3];
    }
    s1 += __shfl_xor_sync(0xFFFFFFFF, s1, 1);
    s1 += __shfl_xor_sync(0xFFFFFFFF, s1, 2);
    s2 += __shfl_xor_sync(0xFFFFFFFF, s2, 1);
    s2 += __shfl_xor_sync(0xFFFFFFFF, s2, 2);
    const float inv1 = 1.0f / s1, inv2 = 1.0f / s2;
#pragma unroll
    for (int nt = 0; nt < 16; nt++) {
        S[nt][0] *= inv1; S[nt][1] *= inv1;
        S[nt][2] *= inv2; S[nt][3] *= inv2;
    }

    const int r1 = w16 + (lane >> 2), r2 = r1 + 8;
    const int jb = (lane & 3) * 2;
    {
        float* p1 = probs + ((size_t)hh * C_DIM + c) * 16384 + (size_t)r1 * 128 + jb;
        float* p2 = probs + ((size_t)hh * C_DIM + c) * 16384 + (size_t)r2 * 128 + jb;
#pragma unroll
        for (int nt = 0; nt < 16; nt++) {
            float2 o1 = { S[nt][0], S[nt][1] };
            float2 o2 = { S[nt][2], S[nt][3] };
            *(float2*)(p1 + nt * 8) = o1;
            *(float2*)(p2 + nt * 8) = o2;
        }
    }

    uint32_t ph[8][4], pl[8][4];
#pragma unroll
    for (int q = 0; q < 8; q++) {
        const int nt0 = 2 * q, nt1 = 2 * q + 1;
        split2(S[nt0][0], S[nt0][1], ph[q][0], pl[q][0]);
        split2(S[nt0][2], S[nt0][3], ph[q][1], pl[q][1]);
        split2(S[nt1][0], S[nt1][1], ph[q][2], pl[q][2]);
        split2(S[nt1][2], S[nt1][3], ph[q][3], pl[q][3]);
    }

    float Cc[8][4];
#pragma unroll
    for (int nf = 0; nf < 8; nf++)
#pragma unroll
        for (int q = 0; q < 4; q++) Cc[nf][q] = 0.0f;

#pragma unroll
    for (int q = 0; q < 8; q++) {
        const uint32_t vbh = (q >= 4) ? VH1 : VH0;
        const uint32_t vbl = (q >= 4) ? VL1 : VL0;
        const int ko = (q & 3) * 16;
#pragma unroll
        for (int df = 0; df < 4; df++) {
            uint32_t off = SMEM_SWZ((df * 16 + b_row) * 128 + (ko + b_k8) * 2);
            uint32_t vh[4], vl[4];
            ldmx4(vh, vbh + off);
            ldmx4(vl, vbl + off);
            mma16816(Cc[df * 2], ph[q], vh);
            mma16816(Cc[df * 2], ph[q], vl);
            mma16816(Cc[df * 2], pl[q], vh);
            mma16816(Cc[df * 2 + 1], ph[q], vh + 2);
            mma16816(Cc[df * 2 + 1], ph[q], vl + 2);
            mma16816(Cc[df * 2 + 1], pl[q], vh + 2);
        }
    }

#pragma unroll
    for (int nf = 0; nf < 8; nf++) {
        const int d = nf * 8 + jb;
        size_t o1 = ((size_t)r1 * C_DIM + c) * E_DIM + hh * 64 + d;
        size_t o2 = ((size_t)r2 * C_DIM + c) * E_DIM + hh * 64 + d;
        uint32_t h0, l0, h1, l1;
        split2(Cc[nf][0], Cc[nf][1], h0, l0);
        split2(Cc[nf][2], Cc[nf][3], h1, l1);
        *(uint32_t*)(Ch + o1) = h0;
        *(uint32_t*)(Cl + o1) = l0;
        *(uint32_t*)(Ch + o2) = h1;
        *(uint32_t*)(Cl + o2) = l1;
    }
}

// ---------------------------------------------------------------------------
extern "C" void kernel_launch(void* const* d_in, const int* in_sizes, int n_in,
                              void* d_out, int out_size)
{
    const float* x  = (const float*)d_in[0];
    const int*   mask = (const int*)d_in[1];
    const float* wq = (const float*)d_in[2];
    const float* bq = (const float*)d_in[3];
    const float* wk = (const float*)d_in[4];
    const float* bk = (const float*)d_in[5];
    const float* wv = (const float*)d_in[6];
    const float* bv = (const float*)d_in[7];
    const float* wo = (const float*)d_in[8];
    const float* bo = (const float*)d_in[9];

    float* out   = (float*)d_out;
    float* probs = (float*)d_out + (size_t)M_TOK * E_DIM;

    __nv_bfloat16 *xh, *xl, *qh, *ql, *kh, *kl, *vh, *vl, *ch, *cl, *wh, *wl;
    cudaGetSymbolAddress((void**)&xh, g_xh);
    cudaGetSymbolAddress((void**)&xl, g_xl);
    cudaGetSymbolAddress((void**)&qh, g_qh);
    cudaGetSymbolAddress((void**)&ql, g_ql);
    cudaGetSymbolAddress((void**)&kh, g_kh);
    cudaGetSymbolAddress((void**)&kl, g_kl);
    cudaGetSymbolAddress((void**)&vh, g_vh);
    cudaGetSymbolAddress((void**)&vl, g_vl);
    cudaGetSymbolAddress((void**)&ch, g_ch);
    cudaGetSymbolAddress((void**)&cl, g_cl);
    cudaGetSymbolAddress((void**)&wh, g_wh);
    cudaGetSymbolAddress((void**)&wl, g_wl);

    static bool attr_set = false;
    if (!attr_set) {
        cudaFuncSetAttribute(attn_kernel, cudaFuncAttributeMaxDynamicSharedMemorySize,
                             ATT_SMEM);
        cudaFuncSetAttribute(gemm_qkv_kernel, cudaFuncAttributeMaxDynamicSharedMemorySize,
                             GEMM_SMEM);
        cudaFuncSetAttribute(gemm_out_kernel, cudaFuncAttributeMaxDynamicSharedMemorySize,
                             GEMM_SMEM);
        attr_set = true;
    }

    const int NX = M_TOK * E_DIM;

    split_kernel<<<4096, 256>>>(x, xh, xl, NX / 4);
    split4_kernel<<<dim3(144, 4), 256>>>(wq, wk, wv, wo, wh, wl, NW_ELEM / 4);

    dim3 gqkv(E_DIM / BN, M_TOK / BM, 3);   // (12, 256, 3)
    gemm_qkv_kernel<<<gqkv, 256, GEMM_SMEM>>>(xh, xl, wh, wl, bq, bk, bv,
                                              qh, ql, kh, kl, vh, vl);

    dim3 gattn(C_DIM, H_DIM);               // (256, 12)
    attn_kernel<<<gattn, 256, ATT_SMEM>>>(qh, ql, kh, kl, vh, vl, mask, probs, ch, cl);

    dim3 gout(E_DIM / BN, M_TOK / BM);      // (12, 256)
    gemm_out_kernel<<<gout, 256, GEMM_SMEM>>>(ch, cl, wh + 3 * (size_t)NW_ELEM,
                                              wl + 3 * (size_t)NW_ELEM, bo, out);
}

// round 8
// speedup vs baseline: 3.4913x; 1.0424x over previous
#include <cuda_runtime.h>
#include <cuda_bf16.h>
#include <cstdint>
#include <math.h>

// Problem constants
#define R_DIM 128
#define C_DIM 256
#define E_DIM 768
#define H_DIM 12
#define D_DIM 64
#define M_TOK (R_DIM * C_DIM)          // 32768
#define SCALING 0.125f
#define NW_ELEM (E_DIM * E_DIM)

// bf16 hi/lo scratch (device globals; no allocation)
__device__ __align__(128) __nv_bfloat16 g_xh[M_TOK * E_DIM];
__device__ __align__(128) __nv_bfloat16 g_xl[M_TOK * E_DIM];
__device__ __align__(128) __nv_bfloat16 g_qh[M_TOK * E_DIM];
__device__ __align__(128) __nv_bfloat16 g_ql[M_TOK * E_DIM];
__device__ __align__(128) __nv_bfloat16 g_kh[M_TOK * E_DIM];
__device__ __align__(128) __nv_bfloat16 g_kl[M_TOK * E_DIM];
__device__ __align__(128) __nv_bfloat16 g_vh[M_TOK * E_DIM];
__device__ __align__(128) __nv_bfloat16 g_vl[M_TOK * E_DIM];
__device__ __align__(128) __nv_bfloat16 g_ch[M_TOK * E_DIM];
__device__ __align__(128) __nv_bfloat16 g_cl[M_TOK * E_DIM];
__device__ __align__(128) __nv_bfloat16 g_wh[4][NW_ELEM];
__device__ __align__(128) __nv_bfloat16 g_wl[4][NW_ELEM];

// ---------------------------------------------------------------------------
// Helpers
// ---------------------------------------------------------------------------
__device__ __forceinline__ uint32_t smem_u32(const void* p) {
    uint32_t a;
    asm("{ .reg .u64 t; cvta.to.shared.u64 t, %1; cvt.u32.u64 %0, t; }" : "=r"(a) : "l"(p));
    return a;
}
__device__ __forceinline__ void cp_async16(uint32_t s, const void* g) {
    size_t ga = __cvta_generic_to_global(g);
    asm volatile("cp.async.cg.shared.global [%0], [%1], 16;" :: "r"(s), "l"(ga));
}
__device__ __forceinline__ void cp_commit() { asm volatile("cp.async.commit_group;" ::: "memory"); }
template <int N> __device__ __forceinline__ void cp_wait() {
    asm volatile("cp.async.wait_group %0;" :: "n"(N) : "memory");
}
__device__ __forceinline__ void ldmx4(uint32_t* r, uint32_t addr) {
    asm volatile("ldmatrix.sync.aligned.m8n8.x4.shared.b16 {%0,%1,%2,%3}, [%4];"
        : "=r"(r[0]), "=r"(r[1]), "=r"(r[2]), "=r"(r[3]) : "r"(addr));
}
__device__ __forceinline__ void ldmx4t(uint32_t* r, uint32_t addr) {
    asm volatile("ldmatrix.sync.aligned.m8n8.x4.trans.shared.b16 {%0,%1,%2,%3}, [%4];"
        : "=r"(r[0]), "=r"(r[1]), "=r"(r[2]), "=r"(r[3]) : "r"(addr));
}
__device__ __forceinline__ void mma16816(float* c, const uint32_t* a, const uint32_t* b) {
    asm volatile("mma.sync.aligned.m16n8k16.row.col.f32.bf16.bf16.f32 "
        "{%0,%1,%2,%3}, {%4,%5,%6,%7}, {%8,%9}, {%0,%1,%2,%3};"
        : "+f"(c[0]), "+f"(c[1]), "+f"(c[2]), "+f"(c[3])
        : "r"(a[0]), "r"(a[1]), "r"(a[2]), "r"(a[3]), "r"(b[0]), "r"(b[1]));
}
__device__ __forceinline__ void split2(float f0, float f1, uint32_t& hi, uint32_t& lo) {
    __nv_bfloat16 h0 = __float2bfloat16(f0);
    __nv_bfloat16 h1 = __float2bfloat16(f1);
    __nv_bfloat16 l0 = __float2bfloat16(f0 - __bfloat162float(h0));
    __nv_bfloat16 l1 = __float2bfloat16(f1 - __bfloat162float(h1));
    __nv_bfloat162 hp = { h0, h1 }, lp = { l0, l1 };
    hi = *(uint32_t*)&hp;
    lo = *(uint32_t*)&lp;
}

#define SMEM_SWZ(o) ((o) ^ (((o) >> 3) & 0x70))

// ---------------------------------------------------------------------------
// Split fp32 -> bf16 hi + bf16 lo (x), and batched variant for the 4 weights
// ---------------------------------------------------------------------------
__global__ __launch_bounds__(256) void split_kernel(
    const float* __restrict__ in, __nv_bfloat16* __restrict__ hi,
    __nv_bfloat16* __restrict__ lo, int n4)
{
    for (int i = blockIdx.x * blockDim.x + threadIdx.x; i < n4; i += gridDim.x * blockDim.x) {
        float4 v = ((const float4*)in)[i];
        __nv_bfloat16 h[4], l[4];
        h[0] = __float2bfloat16(v.x); l[0] = __float2bfloat16(v.x - __bfloat162float(h[0]));
        h[1] = __float2bfloat16(v.y); l[1] = __float2bfloat16(v.y - __bfloat162float(h[1]));
        h[2] = __float2bfloat16(v.z); l[2] = __float2bfloat16(v.z - __bfloat162float(h[2]));
        h[3] = __float2bfloat16(v.w); l[3] = __float2bfloat16(v.w - __bfloat162float(h[3]));
        ((uint2*)hi)[i] = *(uint2*)h;
        ((uint2*)lo)[i] = *(uint2*)l;
    }
}

__global__ __launch_bounds__(256) void split4_kernel(
    const float* __restrict__ w0, const float* __restrict__ w1,
    const float* __restrict__ w2, const float* __restrict__ w3,
    __nv_bfloat16* __restrict__ hbase, __nv_bfloat16* __restrict__ lbase, int n4)
{
    const float* src[4] = { w0, w1, w2, w3 };
    const int b = blockIdx.y;
    const float* in = src[b];
    __nv_bfloat16* hi = hbase + (size_t)b * NW_ELEM;
    __nv_bfloat16* lo = lbase + (size_t)b * NW_ELEM;
    for (int i = blockIdx.x * blockDim.x + threadIdx.x; i < n4; i += gridDim.x * blockDim.x) {
        float4 v = ((const float4*)in)[i];
        __nv_bfloat16 h[4], l[4];
        h[0] = __float2bfloat16(v.x); l[0] = __float2bfloat16(v.x - __bfloat162float(h[0]));
        h[1] = __float2bfloat16(v.y); l[1] = __float2bfloat16(v.y - __bfloat162float(h[1]));
        h[2] = __float2bfloat16(v.z); l[2] = __float2bfloat16(v.z - __bfloat162float(h[2]));
        h[3] = __float2bfloat16(v.w); l[3] = __float2bfloat16(v.w - __bfloat162float(h[3]));
        ((uint2*)hi)[i] = *(uint2*)h;
        ((uint2*)lo)[i] = *(uint2*)l;
    }
}

// ---------------------------------------------------------------------------
// mma.sync GEMM body: acc = sum_k A[m,k]*W[n,k]; out = (acc + bias[n]) * scale
// BM=128, BN=64, BK=64. 256 thr, 4(M)x2(N) warps, warp tile 32x32.
// 3 MMA terms: hh + hl + lh. Stage = 48KB, double-buffered -> 2 CTAs/SM.
// ---------------------------------------------------------------------------
#define GK 768
#define BM 128
#define BN 64
#define BK 64
#define NCHUNK (GK / BK)                 // 12
#define ABUF_BYTES (128 * 128)           // 16384
#define BBUF_BYTES (64 * 128)            // 8192
#define STAGE_BYTES (2 * ABUF_BYTES + 2 * BBUF_BYTES)   // 49152
#define GEMM_SMEM (2 * STAGE_BYTES + 1024)

__device__ __forceinline__ void load_chunk(
    uint32_t stage,
    const __nv_bfloat16* __restrict__ Ah, const __nv_bfloat16* __restrict__ Al,
    const __nv_bfloat16* __restrict__ Bh, const __nv_bfloat16* __restrict__ Bl,
    int m0, int n0, int kc, int t)
{
#pragma unroll
    for (int p = 0; p < 4; p++) {               // A: 128 rows x 8 segs of 16B
        int u = t + p * 256;
        int row = u >> 3, seg = u & 7;
        size_t go = (size_t)(m0 + row) * GK + kc + seg * 8;
        uint32_t so = SMEM_SWZ(row * 128 + seg * 16);
        cp_async16(stage + so, Ah + go);
        cp_async16(stage + ABUF_BYTES + so, Al + go);
    }
#pragma unroll
    for (int p = 0; p < 2; p++) {               // B: 64 rows x 8 segs
        int u = t + p * 256;
        int row = u >> 3, seg = u & 7;
        size_t go = (size_t)(n0 + row) * GK + kc + seg * 8;
        uint32_t so = SMEM_SWZ(row * 128 + seg * 16);
        cp_async16(stage + 2 * ABUF_BYTES + so, Bh + go);
        cp_async16(stage + 2 * ABUF_BYTES + BBUF_BYTES + so, Bl + go);
    }
}

template <bool SPLIT_OUT>
__device__ __forceinline__ void gemm_body(
    const __nv_bfloat16* __restrict__ Ah, const __nv_bfloat16* __restrict__ Al,
    const __nv_bfloat16* __restrict__ Bh, const __nv_bfloat16* __restrict__ Bl,
    const float* __restrict__ bias, float* __restrict__ C,
    __nv_bfloat16* __restrict__ Ch, __nv_bfloat16* __restrict__ Cl,
    float scale, int m0, int n0)
{
    extern __shared__ char smbuf[];
    const uint32_t tiles = (smem_u32(smbuf) + 1023) & ~1023u;
    const int t = threadIdx.x;
    const int lane = t & 31, wid = t >> 5;
    const int wm = wid >> 1, wn = wid & 1;      // 4(M) x 2(N)

    const uint32_t stg[2] = { tiles, tiles + STAGE_BYTES };

    const int a_row = lane & 15;
    const int a_k8 = (lane >> 4) * 8;
    const int b_row = (lane & 7) + ((lane >> 4) & 1) * 8;
    const int b_k8 = ((lane >> 3) & 1) * 8;

    float acc[2][4][4];
#pragma unroll
    for (int mt = 0; mt < 2; mt++)
#pragma unroll
        for (int nt = 0; nt < 4; nt++)
#pragma unroll
            for (int q = 0; q < 4; q++) acc[mt][nt][q] = 0.0f;

    load_chunk(stg[0], Ah, Al, Bh, Bl, m0, n0, 0, t);
    cp_commit();

    for (int c = 0; c < NCHUNK; c++) {
        const int s = c & 1;
        cp_wait<0>();
        __syncthreads();
        if (c + 1 < NCHUNK) {
            load_chunk(stg[s ^ 1], Ah, Al, Bh, Bl, m0, n0, (c + 1) * BK, t);
            cp_commit();
        }

        const uint32_t Abase = stg[s];
        const uint32_t Bbase = stg[s] + 2 * ABUF_BYTES;
#pragma unroll
        for (int kk = 0; kk < 4; kk++) {
            uint32_t ah[2][4], al[2][4];
#pragma unroll
            for (int mt = 0; mt < 2; mt++) {
                uint32_t off = (uint32_t)(wm * 32 + mt * 16 + a_row) * 128
                             + (kk * 16 + a_k8) * 2;
                uint32_t sw = SMEM_SWZ(off);
                ldmx4(ah[mt], Abase + sw);
                ldmx4(al[mt], Abase + ABUF_BYTES + sw);
            }
            uint32_t bh[2][4], bl[2][4];
#pragma unroll
            for (int nb = 0; nb < 2; nb++) {
                uint32_t off = (uint32_t)(wn * 32 + nb * 16 + b_row) * 128
                             + (kk * 16 + b_k8) * 2;
                uint32_t sw = SMEM_SWZ(off);
                ldmx4(bh[nb], Bbase + sw);
                ldmx4(bl[nb], Bbase + BBUF_BYTES + sw);
            }
#pragma unroll
            for (int mt = 0; mt < 2; mt++)
#pragma unroll
                for (int nt = 0; nt < 4; nt++) {
                    const uint32_t* fh = &bh[nt >> 1][(nt & 1) * 2];
                    const uint32_t* fl = &bl[nt >> 1][(nt & 1) * 2];
                    mma16816(acc[mt][nt], ah[mt], fh);
                    mma16816(acc[mt][nt], ah[mt], fl);
                    mma16816(acc[mt][nt], al[mt], fh);
                }
        }
    }

    // epilogue
#pragma unroll
    for (int mt = 0; mt < 2; mt++) {
        const int m = m0 + wm * 32 + mt * 16 + (lane >> 2);
#pragma unroll
        for (int nt = 0; nt < 4; nt++) {
            const int n = n0 + wn * 32 + nt * 8 + (lane & 3) * 2;
            const float b0 = bias[n], b1 = bias[n + 1];
            float v00 = (acc[mt][nt][0] + b0) * scale;
            float v01 = (acc[mt][nt][1] + b1) * scale;
            float v10 = (acc[mt][nt][2] + b0) * scale;
            float v11 = (acc[mt][nt][3] + b1) * scale;
            if (SPLIT_OUT) {
                uint32_t h0, l0, h1, l1;
                split2(v00, v01, h0, l0);
                split2(v10, v11, h1, l1);
                *(uint32_t*)(Ch + (size_t)m * GK + n) = h0;
                *(uint32_t*)(Cl + (size_t)m * GK + n) = l0;
                *(uint32_t*)(Ch + (size_t)(m + 8) * GK + n) = h1;
                *(uint32_t*)(Cl + (size_t)(m + 8) * GK + n) = l1;
            } else {
                float2 o0 = { v00, v01 }, o1 = { v10, v11 };
                *(float2*)(C + (size_t)m * GK + n) = o0;
                *(float2*)(C + (size_t)(m + 8) * GK + n) = o1;
            }
        }
    }
}

// Merged Q/K/V projection: grid.z selects weight/bias/output/scale.
__global__ __launch_bounds__(256, 2)
void gemm_qkv_kernel(
    const __nv_bfloat16* __restrict__ Ah, const __nv_bfloat16* __restrict__ Al,
    const __nv_bfloat16* __restrict__ whb, const __nv_bfloat16* __restrict__ wlb,
    const float* __restrict__ bq, const float* __restrict__ bk, const float* __restrict__ bv,
    __nv_bfloat16* __restrict__ qh, __nv_bfloat16* __restrict__ ql,
    __nv_bfloat16* __restrict__ kh, __nv_bfloat16* __restrict__ kl,
    __nv_bfloat16* __restrict__ vh, __nv_bfloat16* __restrict__ vl)
{
    const int z = blockIdx.z;
    const __nv_bfloat16* Bh = whb + (size_t)z * NW_ELEM;
    const __nv_bfloat16* Bl = wlb + (size_t)z * NW_ELEM;
    const float* bias = (z == 0) ? bq : (z == 1) ? bk : bv;
    __nv_bfloat16* Ch = (z == 0) ? qh : (z == 1) ? kh : vh;
    __nv_bfloat16* Cl = (z == 0) ? ql : (z == 1) ? kl : vl;
    const float scale = (z == 0) ? SCALING : 1.0f;
    gemm_body<true>(Ah, Al, Bh, Bl, bias, nullptr, Ch, Cl, scale,
                    blockIdx.y * BM, blockIdx.x * BN);
}

// Output projection: fp32 result.
__global__ __launch_bounds__(256, 2)
void gemm_out_kernel(
    const __nv_bfloat16* __restrict__ Ah, const __nv_bfloat16* __restrict__ Al,
    const __nv_bfloat16* __restrict__ Bh, const __nv_bfloat16* __restrict__ Bl,
    const float* __restrict__ bias, float* __restrict__ C)
{
    gemm_body<false>(Ah, Al, Bh, Bl, bias, C, nullptr, nullptr, 1.0f,
                     blockIdx.y * BM, blockIdx.x * BN);
}

// ---------------------------------------------------------------------------
// Tensor-core attention: one block per (c, h). 256 threads, 8 warps.
// All of Q,K,V stored row-major [row][d] (128B rows, SW128) via cp.async.
// V consumed through ldmatrix.trans for the P*V B-operand.
// SMEM: QH QL KH KL VH VL = 6 x 16KB = 96KB.
// ---------------------------------------------------------------------------
#define ATT_SMEM (98304 + 1024)

__global__ __launch_bounds__(256, 2) void attn_kernel(
    const __nv_bfloat16* __restrict__ Qh, const __nv_bfloat16* __restrict__ Ql,
    const __nv_bfloat16* __restrict__ Kh, const __nv_bfloat16* __restrict__ Kl,
    const __nv_bfloat16* __restrict__ Vh, const __nv_bfloat16* __restrict__ Vl,
    const int* __restrict__ mask, float* __restrict__ probs,
    __nv_bfloat16* __restrict__ Ch, __nv_bfloat16* __restrict__ Cl)
{
    extern __shared__ char smraw[];
    const uint32_t smb0 = smem_u32(smraw);
    const uint32_t smb = (smb0 + 1023) & ~1023u;

    const uint32_t QH = smb, QL = smb + 16384, KH = smb + 32768, KL = smb + 49152;
    const uint32_t VH = smb + 65536, VL = smb + 81920;

    const int c = blockIdx.x, hh = blockIdx.y;
    const int t = threadIdx.x, lane = t & 31, w = t >> 5;

    // ---- async load Q,K,V (all row-major [row][d], SW128) ----
#pragma unroll
    for (int p = 0; p < 4; p++) {
        int u = t + p * 256;
        int row = u >> 3, seg = u & 7;
        size_t g = ((size_t)row * C_DIM + c) * E_DIM + hh * 64 + seg * 8;
        uint32_t so = SMEM_SWZ(row * 128 + seg * 16);
        cp_async16(QH + so, Qh + g);
        cp_async16(QL + so, Ql + g);
        cp_async16(KH + so, Kh + g);
        cp_async16(KL + so, Kl + g);
        cp_async16(VH + so, Vh + g);
        cp_async16(VL + so, Vl + g);
    }
    cp_commit();
    cp_wait<0>();
    __syncthreads();

    // ---- scores: S[i][j], warp-local full rows ----
    const int w16 = w * 16;
    const int a_row = lane & 15, a_k8 = (lane >> 4) * 8;
    const int b_row = (lane & 7) + ((lane >> 4) & 1) * 8, b_k8 = ((lane >> 3) & 1) * 8;

    float S[16][4];
#pragma unroll
    for (int nt = 0; nt < 16; nt++)
#pragma unroll
        for (int q = 0; q < 4; q++) S[nt][q] = 0.0f;

#pragma unroll
    for (int kk = 0; kk < 4; kk++) {
        uint32_t ao = SMEM_SWZ((w16 + a_row) * 128 + (kk * 16 + a_k8) * 2);
        uint32_t ah[4], al[4];
        ldmx4(ah, QH + ao);
        ldmx4(al, QL + ao);
#pragma unroll
        for (int nb = 0; nb < 8; nb++) {
            uint32_t bo = SMEM_SWZ((nb * 16 + b_row) * 128 + (kk * 16 + b_k8) * 2);
            uint32_t bh[4], bl[4];
            ldmx4(bh, KH + bo);
            ldmx4(bl, KL + bo);
            mma16816(S[nb * 2], ah, bh);
            mma16816(S[nb * 2], ah, bl);
            mma16816(S[nb * 2], al, bh);
            mma16816(S[nb * 2 + 1], ah, bh + 2);
            mma16816(S[nb * 2 + 1], ah, bl + 2);
            mma16816(S[nb * 2 + 1], al, bh + 2);
        }
    }

    // ---- mask: padded column -> uniform softmax (matches reference) ----
    if (mask[c] != 0) {
#pragma unroll
        for (int nt = 0; nt < 16; nt++)
#pragma unroll
            for (int q = 0; q < 4; q++) S[nt][q] = 0.0f;
    }

    // ---- register softmax over j (reduce across lane&3 quads) ----
    float mx1 = -1e30f, mx2 = -1e30f;
#pragma unroll
    for (int nt = 0; nt < 16; nt++) {
        mx1 = fmaxf(mx1, fmaxf(S[nt][0], S[nt][1]));
        mx2 = fmaxf(mx2, fmaxf(S[nt][2], S[nt][3]));
    }
    mx1 = fmaxf(mx1, __shfl_xor_sync(0xFFFFFFFF, mx1, 1));
    mx1 = fmaxf(mx1, __shfl_xor_sync(0xFFFFFFFF, mx1, 2));
    mx2 = fmaxf(mx2, __shfl_xor_sync(0xFFFFFFFF, mx2, 1));
    mx2 = fmaxf(mx2, __shfl_xor_sync(0xFFFFFFFF, mx2, 2));

    float s1 = 0.0f, s2 = 0.0f;
#pragma unroll
    for (int nt = 0; nt < 16; nt++) {
        S[nt][0] = __expf(S[nt][0] - mx1); s1 += S[nt][0];
        S[nt][1] = __expf(S[nt][1] - mx1); s1 += S[nt][1];
        S[nt][2] = __expf(S[nt][2] - mx2); s2 += S[nt][2];
        S[nt][3] = __expf(S[nt][3] - mx2); s2 += S[nt][3];
    }
    s1 += __shfl_xor_sync(0xFFFFFFFF, s1, 1);
    s1 += __shfl_xor_sync(0xFFFFFFFF, s1, 2);
    s2 += __shfl_xor_sync(0xFFFFFFFF, s2, 1);
    s2 += __shfl_xor_sync(0xFFFFFFFF, s2, 2);
    const float inv1 = 1.0f / s1, inv2 = 1.0f / s2;
#pragma unroll
    for (int nt = 0; nt < 16; nt++) {
        S[nt][0] *= inv1; S[nt][1] *= inv1;
        S[nt][2] *= inv2; S[nt][3] *= inv2;
    }

    // ---- write attn_probs [h][c][i][j] straight from registers ----
    const int r1 = w16 + (lane >> 2), r2 = r1 + 8;
    const int jb = (lane & 3) * 2;
    {
        float* p1 = probs + ((size_t)hh * C_DIM + c) * 16384 + (size_t)r1 * 128 + jb;
        float* p2 = probs + ((size_t)hh * C_DIM + c) * 16384 + (size_t)r2 * 128 + jb;
#pragma unroll
        for (int nt = 0; nt < 16; nt++) {
            float2 o1 = { S[nt][0], S[nt][1] };
            float2 o2 = { S[nt][2], S[nt][3] };
            *(float2*)(p1 + nt * 8) = o1;
            *(float2*)(p2 + nt * 8) = o2;
        }
    }

    // ---- pack P into hi/lo A-fragments (register-only) ----
    uint32_t ph[8][4], pl[8][4];
#pragma unroll
    for (int q = 0; q < 8; q++) {
        const int nt0 = 2 * q, nt1 = 2 * q + 1;
        split2(S[nt0][0], S[nt0][1], ph[q][0], pl[q][0]);
        split2(S[nt0][2], S[nt0][3], ph[q][1], pl[q][1]);
        split2(S[nt1][0], S[nt1][1], ph[q][2], pl[q][2]);
        split2(S[nt1][2], S[nt1][3], ph[q][3], pl[q][3]);
    }

    // ---- context: C[i][d] = sum_j P[i][j] * V[j][d]  (ldmatrix.trans B) ----
    const int v_row = (lane & 7) + ((lane >> 3) & 1) * 8;   // j within 16-tile
    const int v_half = (lane >> 4) * 16;                    // byte offset: d-chunk

    float Cc[8][4];
#pragma unroll
    for (int nf = 0; nf < 8; nf++)
#pragma unroll
        for (int q = 0; q < 4; q++) Cc[nf][q] = 0.0f;

#pragma unroll
    for (int q = 0; q < 8; q++) {           // j-tiles of 16
#pragma unroll
        for (int df = 0; df < 4; df++) {    // d-tiles of 16 (two n8 chunks)
            uint32_t off = SMEM_SWZ((q * 16 + v_row) * 128 + df * 32 + v_half);
            uint32_t vh[4], vl[4];
            ldmx4t(vh, VH + off);
            ldmx4t(vl, VL + off);
            mma16816(Cc[df * 2], ph[q], vh);
            mma16816(Cc[df * 2], ph[q], vl);
            mma16816(Cc[df * 2], pl[q], vh);
            mma16816(Cc[df * 2 + 1], ph[q], vh + 2);
            mma16816(Cc[df * 2 + 1], ph[q], vl + 2);
            mma16816(Cc[df * 2 + 1], pl[q], vh + 2);
        }
    }

    // ---- write ctx as bf16 hi/lo (fused split) ----
#pragma unroll
    for (int nf = 0; nf < 8; nf++) {
        const int d = nf * 8 + jb;
        size_t o1 = ((size_t)r1 * C_DIM + c) * E_DIM + hh * 64 + d;
        size_t o2 = ((size_t)r2 * C_DIM + c) * E_DIM + hh * 64 + d;
        uint32_t h0, l0, h1, l1;
        split2(Cc[nf][0], Cc[nf][1], h0, l0);
        split2(Cc[nf][2], Cc[nf][3], h1, l1);
        *(uint32_t*)(Ch + o1) = h0;
        *(uint32_t*)(Cl + o1) = l0;
        *(uint32_t*)(Ch + o2) = h1;
        *(uint32_t*)(Cl + o2) = l1;
    }
}

// ---------------------------------------------------------------------------
extern "C" void kernel_launch(void* const* d_in, const int* in_sizes, int n_in,
                              void* d_out, int out_size)
{
    const float* x  = (const float*)d_in[0];
    const int*   mask = (const int*)d_in[1];
    const float* wq = (const float*)d_in[2];
    const float* bq = (const float*)d_in[3];
    const float* wk = (const float*)d_in[4];
    const float* bk = (const float*)d_in[5];
    const float* wv = (const float*)d_in[6];
    const float* bv = (const float*)d_in[7];
    const float* wo = (const float*)d_in[8];
    const float* bo = (const float*)d_in[9];

    float* out   = (float*)d_out;
    float* probs = (float*)d_out + (size_t)M_TOK * E_DIM;

    __nv_bfloat16 *xh, *xl, *qh, *ql, *kh, *kl, *vh, *vl, *ch, *cl, *wh, *wl;
    cudaGetSymbolAddress((void**)&xh, g_xh);
    cudaGetSymbolAddress((void**)&xl, g_xl);
    cudaGetSymbolAddress((void**)&qh, g_qh);
    cudaGetSymbolAddress((void**)&ql, g_ql);
    cudaGetSymbolAddress((void**)&kh, g_kh);
    cudaGetSymbolAddress((void**)&kl, g_kl);
    cudaGetSymbolAddress((void**)&vh, g_vh);
    cudaGetSymbolAddress((void**)&vl, g_vl);
    cudaGetSymbolAddress((void**)&ch, g_ch);
    cudaGetSymbolAddress((void**)&cl, g_cl);
    cudaGetSymbolAddress((void**)&wh, g_wh);
    cudaGetSymbolAddress((void**)&wl, g_wl);

    static bool attr_set = false;
    if (!attr_set) {
        cudaFuncSetAttribute(attn_kernel, cudaFuncAttributeMaxDynamicSharedMemorySize,
                             ATT_SMEM);
        cudaFuncSetAttribute(gemm_qkv_kernel, cudaFuncAttributeMaxDynamicSharedMemorySize,
                             GEMM_SMEM);
        cudaFuncSetAttribute(gemm_out_kernel, cudaFuncAttributeMaxDynamicSharedMemorySize,
                             GEMM_SMEM);
        attr_set = true;
    }

    const int NX = M_TOK * E_DIM;

    split_kernel<<<4096, 256>>>(x, xh, xl, NX / 4);
    split4_kernel<<<dim3(144, 4), 256>>>(wq, wk, wv, wo, wh, wl, NW_ELEM / 4);

    dim3 gqkv(E_DIM / BN, M_TOK / BM, 3);   // (12, 256, 3)
    gemm_qkv_kernel<<<gqkv, 256, GEMM_SMEM>>>(xh, xl, wh, wl, bq, bk, bv,
                                              qh, ql, kh, kl, vh, vl);

    dim3 gattn(C_DIM, H_DIM);               // (256, 12)
    attn_kernel<<<gattn, 256, ATT_SMEM>>>(qh, ql, kh, kl, vh, vl, mask, probs, ch, cl);

    dim3 gout(E_DIM / BN, M_TOK / BM);      // (12, 256)
    gemm_out_kernel<<<gout, 256, GEMM_SMEM>>>(ch, cl, wh + 3 * (size_t)NW_ELEM,
                                              wl + 3 * (size_t)NW_ELEM, bo, out);
}